// round 12
// baseline (speedup 1.0000x reference)
#include <cuda_runtime.h>
#include <cuda_fp16.h>
#include <math.h>
#include <stdint.h>

#define BATCH 64
#define SEQ 197
#define NPATCH 196
#define HID 768
#define NH 12
#define DH 64
#define DFF 3072
#define NL 4
#define OUTD 1000

#define BS (BATCH*SEQ)      // 12608
#define BP (BATCH*NPATCH)   // 12544

#define WPN (768*768)
#define W1N (NL*HID*DFF)
#define W2N (NL*DFF*HID)
#define WTOT (WPN + W1N + W2N)

// ---------------- scratch (static device globals; no allocations) ----------------
__device__ float  g_out[(size_t)BS*HID];
__device__ __half g_xh [(size_t)BS*HID];     // half activations (ln out / patches)
__device__ __half g_ffh[(size_t)BS*DFF];     // half FF1 output
__device__ float  g_q  [(size_t)BS*HID];
__device__ float  g_k  [(size_t)BS*HID];
__device__ float  g_v  [(size_t)BS*HID];
__device__ float  g_att[(size_t)BATCH*NH*SEQ*SEQ];
__device__ __half g_wh [(size_t)WTOT];       // half weights {Wp, W1, W2}

// ---------------- weight convert: {Wp, W1, W2} -> g_wh (half) ----------------
__global__ void convert_weights_kernel(const float* __restrict__ Wp,
                                       const float* __restrict__ W1,
                                       const float* __restrict__ W2,
                                       __half* __restrict__ dst) {
    size_t idx = (size_t)blockIdx.x * 256 + threadIdx.x;
    if (idx >= (size_t)WTOT) return;
    float v;
    if (idx < WPN)            v = Wp[idx];
    else if (idx < WPN + W1N) v = W1[idx - WPN];
    else                      v = W2[idx - WPN - W1N];
    dst[idx] = __float2half(v);
}

// ---------------- patchify -> half patches ----------------
__global__ void patchify_kernel(const float* __restrict__ img, __half* __restrict__ patches) {
    int idx = blockIdx.x * 256 + threadIdx.x;
    if (idx >= BP * HID) return;
    int k = idx % HID;
    int m = idx / HID;
    int b = m / NPATCH, p = m % NPATCH;
    int pr = p / 14, pc = p % 14;
    int c = k >> 8;
    int ij = k & 255;
    int i = ij >> 4, j = ij & 15;
    patches[idx] = __float2half(img[(((b*3 + c)*224) + pr*16 + i)*224 + pc*16 + j]);
}

__device__ __forceinline__ float gelu_exact(float x) {
    return 0.5f * x * (1.0f + erff(x * 0.7071067811865476f));
}

__device__ __forceinline__ void mma_f16(float c[4], uint32_t a0, uint32_t a1,
        uint32_t a2, uint32_t a3, uint32_t b0, uint32_t b1) {
    asm volatile(
        "mma.sync.aligned.m16n8k16.row.col.f32.f16.f16.f32 "
        "{%0,%1,%2,%3}, {%4,%5,%6,%7}, {%8,%9}, {%0,%1,%2,%3};"
        : "+f"(c[0]), "+f"(c[1]), "+f"(c[2]), "+f"(c[3])
        : "r"(a0), "r"(a1), "r"(a2), "r"(a3), "r"(b0), "r"(b1));
}

__device__ __forceinline__ void ldsm4(uint32_t r[4], uint32_t addr) {
    asm volatile("ldmatrix.sync.aligned.m8n8.x4.shared.b16 {%0,%1,%2,%3}, [%4];"
        : "=r"(r[0]), "=r"(r[1]), "=r"(r[2]), "=r"(r[3]) : "r"(addr));
}
__device__ __forceinline__ void ldsm4t(uint32_t r[4], uint32_t addr) {
    asm volatile("ldmatrix.sync.aligned.m8n8.x4.trans.shared.b16 {%0,%1,%2,%3}, [%4];"
        : "=r"(r[0]), "=r"(r[1]), "=r"(r[2]), "=r"(r[3]) : "r"(addr));
}

__device__ __forceinline__ void cp16(void* dst, const void* src) {
    uint32_t d = (uint32_t)__cvta_generic_to_shared(dst);
    asm volatile("cp.async.cg.shared.global [%0], [%1], 16;" :: "r"(d), "l"(src));
}
__device__ __forceinline__ void cp_commit() { asm volatile("cp.async.commit_group;"); }
__device__ __forceinline__ void cp_wait1()  { asm volatile("cp.async.wait_group 1;"); }

// ---------------- FP16 tensor-core GEMM, 3-stage cp.async + ldmatrix ----------
// C = act(A[M,K]h @ B[K,N]h + bias). N%128==0, K%32==0, M guarded.
// 256x128 block, Ktile=32, 16 warps (4x4), warp tile 64x32, fp32 accum.
#define ASTR 40     // A row stride, halves (80B: conflict-free ldmatrix groups)
#define BSTR 264    // B row stride, halves (528B)
#define A_STAGE_H (256*ASTR)   // 10240 halves
#define B_STAGE_H (32*BSTR)    // 8448 halves
#define A_STAGE_B (A_STAGE_H*2)
#define B_STAGE_B (B_STAGE_H*2)
#define GEMM_SMEM_BYTES (3*(A_STAGE_B + B_STAGE_B))   // 112128

template<int ACT, int RESID, int OUTH>
__global__ void __launch_bounds__(512) gemm_f16(
        const __half* __restrict__ A, const __half* __restrict__ B,
        const float* __restrict__ bias, void* __restrict__ Cv,
        int M, int N, int K)
{
    extern __shared__ uint32_t smem_dyn[];
    __half* Ash = (__half*)smem_dyn;                 // [3][256][ASTR]
    __half* Bsh = (__half*)smem_dyn + 3*A_STAGE_H;   // [3][32][BSTR]
    uint32_t s_base = (uint32_t)__cvta_generic_to_shared(smem_dyn);
    uint32_t a_s32 = s_base;
    uint32_t b_s32 = s_base + 3*A_STAGE_B;

    int tid  = threadIdx.x;
    int lane = tid & 31;
    int warp = tid >> 5;
    int warp_m = (warp >> 2) * 64;      // 0,64,128,192
    int warp_n = (warp & 3) * 32;       // 0,32,64,96
    int gid = lane >> 2, tig = lane & 3;

    int row0 = blockIdx.y * 256, col0 = blockIdx.x * 128;

    // cp.async mapping: A = 2 ops/thread, B = 1 op/thread
    int rowA = tid >> 1;                // 0..255
    int akh  = (tid & 1) * 16;          // halves 0 or 16
    int arow = row0 + rowA; if (arow >= M) arow = M - 1;
    const __half* Aptr = A + (size_t)arow * K + akh;
    int rowB = tid >> 4;                // 0..31
    int nch  = (tid & 15) * 8;          // halves 0..120
    const __half* Bptr = B + (size_t)rowB * N + col0 + nch;

    // ldmatrix per-lane offsets (bytes)
    uint32_t aoff = (uint32_t)((lane & 15) * (ASTR*2) + (lane >> 4) * 16);
    uint32_t boff = (uint32_t)((lane & 15) * (BSTR*2) + (lane >> 4) * 16);

    float acc[4][4][4];
#pragma unroll
    for (int i = 0; i < 4; i++)
#pragma unroll
        for (int j = 0; j < 4; j++)
#pragma unroll
            for (int r = 0; r < 4; r++) acc[i][j][r] = 0.f;

    int nt = K >> 5;   // Ktile = 32

    // prologue: stages 0,1
#pragma unroll
    for (int s = 0; s < 2; s++) {
        const __half* ap = Aptr + (size_t)s * 32;
        cp16(Ash + (size_t)s*A_STAGE_H + rowA*ASTR + akh,     ap);
        cp16(Ash + (size_t)s*A_STAGE_H + rowA*ASTR + akh + 8, ap + 8);
        const __half* bp = Bptr + (size_t)s * 32 * N;
        cp16(Bsh + (size_t)s*B_STAGE_H + rowB*BSTR + nch, bp);
        cp_commit();
    }

    for (int t = 0; t < nt; t++) {
        cp_wait1();
        __syncthreads();
        int buf = t % 3;
        uint32_t abase = a_s32 + buf*A_STAGE_B + warp_m*(ASTR*2) + aoff;
        uint32_t bbase = b_s32 + buf*B_STAGE_B + warp_n*2 + boff;
#pragma unroll
        for (int k16 = 0; k16 < 2; k16++) {
            uint32_t ak = abase + k16*32;              // +16 halves
            uint32_t bk = bbase + k16*16*(BSTR*2);     // +16 k-rows
            uint32_t afr[4][4];
#pragma unroll
            for (int ma = 0; ma < 4; ma++)
                ldsm4(afr[ma], ak + ma*16*(ASTR*2));
            uint32_t bq[2][4];
#pragma unroll
            for (int nb = 0; nb < 2; nb++)
                ldsm4t(bq[nb], bk + nb*32);
#pragma unroll
            for (int ma = 0; ma < 4; ma++) {
#pragma unroll
                for (int nb = 0; nb < 2; nb++) {
                    mma_f16(acc[ma][nb*2],   afr[ma][0], afr[ma][1], afr[ma][2], afr[ma][3],
                            bq[nb][0], bq[nb][1]);
                    mma_f16(acc[ma][nb*2+1], afr[ma][0], afr[ma][1], afr[ma][2], afr[ma][3],
                            bq[nb][2], bq[nb][3]);
                }
            }
        }
        if (t + 2 < nt) {
            int s = (t + 2) % 3;
            const __half* ap = Aptr + (size_t)(t + 2) * 32;
            cp16(Ash + (size_t)s*A_STAGE_H + rowA*ASTR + akh,     ap);
            cp16(Ash + (size_t)s*A_STAGE_H + rowA*ASTR + akh + 8, ap + 8);
            const __half* bp = Bptr + (size_t)(t + 2) * 32 * N;
            cp16(Bsh + (size_t)s*B_STAGE_H + rowB*BSTR + nch, bp);
        }
        cp_commit();
    }

    // epilogue
#pragma unroll
    for (int ma = 0; ma < 4; ma++) {
        int r_lo = row0 + warp_m + ma * 16 + gid;
        int r_hi = r_lo + 8;
#pragma unroll
        for (int na = 0; na < 4; na++) {
            int c = col0 + warp_n + na * 8 + tig * 2;
            float bc0 = bias[c], bc1 = bias[c + 1];
            if (r_lo < M) {
                float v0 = acc[ma][na][0] + bc0;
                float v1 = acc[ma][na][1] + bc1;
                size_t off = (size_t)r_lo * N + c;
                if (ACT == 1) { v0 = gelu_exact(v0); v1 = gelu_exact(v1); }
                if (OUTH) {
                    *(__half2*)((__half*)Cv + off) = __floats2half2_rn(v0, v1);
                } else if (RESID) {
                    ((float*)Cv)[off] += v0; ((float*)Cv)[off + 1] += v1;
                } else {
                    ((float*)Cv)[off]  = v0; ((float*)Cv)[off + 1]  = v1;
                }
            }
            if (r_hi < M) {
                float v2 = acc[ma][na][2] + bc0;
                float v3 = acc[ma][na][3] + bc1;
                size_t off = (size_t)r_hi * N + c;
                if (ACT == 1) { v2 = gelu_exact(v2); v3 = gelu_exact(v3); }
                if (OUTH) {
                    *(__half2*)((__half*)Cv + off) = __floats2half2_rn(v2, v3);
                } else if (RESID) {
                    ((float*)Cv)[off] += v2; ((float*)Cv)[off + 1] += v3;
                } else {
                    ((float*)Cv)[off]  = v2; ((float*)Cv)[off + 1]  = v3;
                }
            }
        }
    }
}

// ---------------- pos-emb + cls assembly ----------------
__global__ void add_pos_cls_kernel(const float* __restrict__ tok,
                                   const float* __restrict__ cls,
                                   float* __restrict__ outp) {
    int idx = blockIdx.x * 256 + threadIdx.x;
    if (idx >= BS * HID) return;
    int d = idx % HID;
    int r = idx / HID;
    int b = r / SEQ, s = r % SEQ;
    float jf = (float)((d >> 1) << 1);
    float denom = powf(10000.0f, jf * (1.0f/768.0f));
    float ang = (float)s / denom;
    float pos = (d & 1) ? cosf(ang) : sinf(ang);
    float base = (s == 0) ? cls[d] : tok[(size_t)(b*NPATCH + s - 1)*HID + d];
    outp[idx] = base + pos;
}

// ---------------- LayerNorm -> half output ----------------
__global__ void __launch_bounds__(256) ln_kernel(const float* __restrict__ in,
        const float* __restrict__ gam, const float* __restrict__ bet,
        __half* __restrict__ outp) {
    __shared__ float red[16];
    int row = blockIdx.x;
    int tid = threadIdx.x;
    const float* x = in + (size_t)row * HID;
    float v0 = x[tid], v1 = x[tid+256], v2 = x[tid+512];
    float s  = v0 + v1 + v2;
    float ss = v0*v0 + v1*v1 + v2*v2;
#pragma unroll
    for (int o = 16; o; o >>= 1) {
        s  += __shfl_xor_sync(0xffffffffu, s, o);
        ss += __shfl_xor_sync(0xffffffffu, ss, o);
    }
    if ((tid & 31) == 0) { red[tid>>5] = s; red[8 + (tid>>5)] = ss; }
    __syncthreads();
    if (tid < 32) {
        float a  = (tid < 8) ? red[tid]   : 0.f;
        float bb = (tid < 8) ? red[8+tid] : 0.f;
#pragma unroll
        for (int o = 4; o; o >>= 1) {
            a  += __shfl_xor_sync(0xffffffffu, a, o);
            bb += __shfl_xor_sync(0xffffffffu, bb, o);
        }
        if (tid == 0) { red[0] = a; red[1] = bb; }
    }
    __syncthreads();
    float mean = red[0] * (1.0f/768.0f);
    float var  = red[1] * (1.0f/768.0f) - mean*mean;
    float rstd = rsqrtf(var + 1e-5f);
    __half* o = outp + (size_t)row * HID;
    o[tid]     = __float2half((v0 - mean)*rstd*gam[tid]     + bet[tid]);
    o[tid+256] = __float2half((v1 - mean)*rstd*gam[tid+256] + bet[tid+256]);
    o[tid+512] = __float2half((v2 - mean)*rstd*gam[tid+512] + bet[tid+512]);
}

// ---------------- fused QKV per-head projection (half x, fp32 W) ----------------
__global__ void __launch_bounds__(256) qkv_fused_kernel(const __half* __restrict__ x,
        const float* __restrict__ Wq, const float* __restrict__ bq, float* __restrict__ oq,
        const float* __restrict__ Wk, const float* __restrict__ bk, float* __restrict__ ok,
        const float* __restrict__ Wv, const float* __restrict__ bv, float* __restrict__ ov) {
    const float* W; const float* bias; float* outp;
    if (blockIdx.z == 0)      { W = Wq; bias = bq; outp = oq; }
    else if (blockIdx.z == 1) { W = Wk; bias = bk; outp = ok; }
    else                      { W = Wv; bias = bv; outp = ov; }

    __shared__ __align__(16) float Xs[DH][68];
    __shared__ __align__(16) float Ws[DH][68];
    int h = blockIdx.y;
    int row0 = blockIdx.x * 64;
    int tid = threadIdx.x;
    {
        int r  = tid >> 2;
        int d0 = (tid & 3) * 16;
        const __half* src = x + (size_t)(row0 + r)*HID + h*DH + d0;
        const float* wsrc = W + (size_t)h*DH*DH + (size_t)r*DH + d0;
#pragma unroll
        for (int q8 = 0; q8 < 2; q8++) {
            uint4 u = *(const uint4*)(src + q8*8);
#pragma unroll
            for (int j = 0; j < 4; j++) {
                __half2 h2 = ((const __half2*)&u)[j];
                float2 f2 = __half22float2(h2);
                Xs[d0 + q8*8 + j*2    ][r] = f2.x;
                Xs[d0 + q8*8 + j*2 + 1][r] = f2.y;
            }
        }
#pragma unroll
        for (int u2 = 0; u2 < 4; u2++) {
            float4 w = *(const float4*)(wsrc + u2*4);
            Ws[d0+u2*4+0][r]=w.x; Ws[d0+u2*4+1][r]=w.y; Ws[d0+u2*4+2][r]=w.z; Ws[d0+u2*4+3][r]=w.w;
        }
    }
    __syncthreads();
    int tr = (tid >> 4) * 4;
    int tc = (tid & 15) * 4;
    float acc[4][4] = {{0.f}};
#pragma unroll
    for (int d = 0; d < DH; d++) {
        float4 av = *(const float4*)&Xs[d][tr];
        float4 bv4 = *(const float4*)&Ws[d][tc];
        acc[0][0] += av.x*bv4.x; acc[0][1] += av.x*bv4.y; acc[0][2] += av.x*bv4.z; acc[0][3] += av.x*bv4.w;
        acc[1][0] += av.y*bv4.x; acc[1][1] += av.y*bv4.y; acc[1][2] += av.y*bv4.z; acc[1][3] += av.y*bv4.w;
        acc[2][0] += av.z*bv4.x; acc[2][1] += av.z*bv4.y; acc[2][2] += av.z*bv4.z; acc[2][3] += av.z*bv4.w;
        acc[3][0] += av.w*bv4.x; acc[3][1] += av.w*bv4.y; acc[3][2] += av.w*bv4.z; acc[3][3] += av.w*bv4.w;
    }
#pragma unroll
    for (int i = 0; i < 4; i++) {
        float* dst = outp + (size_t)(row0 + tr + i)*HID + h*DH + tc;
#pragma unroll
        for (int j = 0; j < 4; j++) dst[j] = acc[i][j] + bias[h*DH + tc + j];
    }
}

// ---------------- attention scores + row softmax ----------------
__global__ void __launch_bounds__(256) attn_score_kernel(const float* __restrict__ q,
        const float* __restrict__ kmat, float* __restrict__ att) {
    __shared__ float qs[DH][33];
    __shared__ __align__(16) float ks[DH][36];
    __shared__ float sc[32][200];
    int bh = blockIdx.y;
    int b = bh / NH, h = bh % NH;
    int i0 = blockIdx.x * 32;
    int tid = threadIdx.x;
    {
        int r = tid >> 3;
        int d0 = (tid & 7) * 8;
        int i = i0 + r; if (i >= SEQ) i = 0;
        const float* src = q + (size_t)(b*SEQ + i)*HID + h*DH + d0;
        float4 a = *(const float4*)src;
        float4 c = *(const float4*)(src + 4);
        qs[d0+0][r]=a.x; qs[d0+1][r]=a.y; qs[d0+2][r]=a.z; qs[d0+3][r]=a.w;
        qs[d0+4][r]=c.x; qs[d0+5][r]=c.y; qs[d0+6][r]=c.z; qs[d0+7][r]=c.w;
    }
    const float scale = 0.125f;
    int ti  = tid >> 3;
    int tj4 = (tid & 7) * 4;
    for (int j0 = 0; j0 < SEQ; j0 += 32) {
        __syncthreads();
        {
            int r = tid >> 3;
            int d0 = (tid & 7) * 8;
            int j = j0 + r; if (j >= SEQ) j = 0;
            const float* src = kmat + (size_t)(b*SEQ + j)*HID + h*DH + d0;
            float4 a = *(const float4*)src;
            float4 c = *(const float4*)(src + 4);
            ks[d0+0][r]=a.x; ks[d0+1][r]=a.y; ks[d0+2][r]=a.z; ks[d0+3][r]=a.w;
            ks[d0+4][r]=c.x; ks[d0+5][r]=c.y; ks[d0+6][r]=c.z; ks[d0+7][r]=c.w;
        }
        __syncthreads();
        float acc0=0.f, acc1=0.f, acc2=0.f, acc3=0.f;
#pragma unroll
        for (int d = 0; d < DH; d++) {
            float a = qs[d][ti];
            float4 bv = *(const float4*)&ks[d][tj4];
            acc0 += a*bv.x; acc1 += a*bv.y; acc2 += a*bv.z; acc3 += a*bv.w;
        }
        if (j0 + tj4 + 0 < SEQ) sc[ti][j0+tj4+0] = acc0*scale;
        if (j0 + tj4 + 1 < SEQ) sc[ti][j0+tj4+1] = acc1*scale;
        if (j0 + tj4 + 2 < SEQ) sc[ti][j0+tj4+2] = acc2*scale;
        if (j0 + tj4 + 3 < SEQ) sc[ti][j0+tj4+3] = acc3*scale;
    }
    __syncthreads();
    int w = tid >> 5, lane = tid & 31;
    for (int rq = 0; rq < 4; rq++) {
        int row = w*4 + rq;
        int i = i0 + row;
        if (i >= SEQ) continue;
        float m = -1e30f;
        for (int j = lane; j < SEQ; j += 32) m = fmaxf(m, sc[row][j]);
#pragma unroll
        for (int o = 16; o; o >>= 1) m = fmaxf(m, __shfl_xor_sync(0xffffffffu, m, o));
        float s = 0.f;
        for (int j = lane; j < SEQ; j += 32) { float e = expf(sc[row][j] - m); sc[row][j] = e; s += e; }
#pragma unroll
        for (int o = 16; o; o >>= 1) s += __shfl_xor_sync(0xffffffffu, s, o);
        float inv = 1.0f / s;
        float* dst = att + ((size_t)bh*SEQ + i)*SEQ;
        for (int j = lane; j < SEQ; j += 32) dst[j] = sc[row][j]*inv;
    }
}

// ---------------- AV ----------------
__global__ void __launch_bounds__(256) attn_av_kernel(const float* __restrict__ att,
        const float* __restrict__ v, float* __restrict__ outp) {
    __shared__ float as_[32][33];
    __shared__ __align__(16) float vs[32][68];
    int bh = blockIdx.y;
    int b = bh / NH, h = bh % NH;
    int i0 = blockIdx.x * 32;
    int tid = threadIdx.x;
    int tr = (tid >> 4) * 2;
    int tc = (tid & 15) * 4;
    float acc[2][4] = {{0.f}};
    for (int t0 = 0; t0 < SEQ; t0 += 32) {
        __syncthreads();
        {
            int i = tid >> 3;
            int t4 = (tid & 7) * 4;
            int gi = i0 + i;
#pragma unroll
            for (int u = 0; u < 4; u++) {
                int t = t0 + t4 + u;
                as_[i][t4+u] = (gi < SEQ && t < SEQ) ? att[((size_t)bh*SEQ + gi)*SEQ + t] : 0.f;
            }
        }
        {
            int t = tid >> 3;
            int e0 = (tid & 7) * 8;
            int gt = t0 + t;
            if (gt < SEQ) {
                const float* src = v + (size_t)(b*SEQ + gt)*HID + h*DH + e0;
                float4 a = *(const float4*)src;
                float4 c = *(const float4*)(src + 4);
                vs[t][e0+0]=a.x; vs[t][e0+1]=a.y; vs[t][e0+2]=a.z; vs[t][e0+3]=a.w;
                vs[t][e0+4]=c.x; vs[t][e0+5]=c.y; vs[t][e0+6]=c.z; vs[t][e0+7]=c.w;
            } else {
#pragma unroll
                for (int u = 0; u < 8; u++) vs[t][e0+u] = 0.f;
            }
        }
        __syncthreads();
#pragma unroll
        for (int tt = 0; tt < 32; tt++) {
            float a0 = as_[tr][tt], a1 = as_[tr+1][tt];
            float4 bv = *(const float4*)&vs[tt][tc];
            acc[0][0] += a0*bv.x; acc[0][1] += a0*bv.y; acc[0][2] += a0*bv.z; acc[0][3] += a0*bv.w;
            acc[1][0] += a1*bv.x; acc[1][1] += a1*bv.y; acc[1][2] += a1*bv.z; acc[1][3] += a1*bv.w;
        }
    }
#pragma unroll
    for (int u = 0; u < 2; u++) {
        int i = i0 + tr + u;
        if (i < SEQ) {
            float* dst = outp + (size_t)(b*SEQ + i)*HID + h*DH + tc;
            dst[0] += acc[u][0]; dst[1] += acc[u][1]; dst[2] += acc[u][2]; dst[3] += acc[u][3];
        }
    }
}

// ---------------- head ----------------
__global__ void __launch_bounds__(256) head_kernel(const float* __restrict__ xin,
        const float* __restrict__ Wo, const float* __restrict__ bo,
        float* __restrict__ res) {
    __shared__ float xs[HID];
    __shared__ float logits[OUTD];
    __shared__ float red[8];
    int b = blockIdx.x;
    int tid = threadIdx.x;
    const float* src = xin + (size_t)b*SEQ*HID;
    xs[tid] = src[tid]; xs[tid+256] = src[tid+256]; xs[tid+512] = src[tid+512];
    __syncthreads();
    for (int c = tid; c < OUTD; c += 256) {
        float acc = bo[c];
#pragma unroll 8
        for (int k2 = 0; k2 < HID; k2++) acc += xs[k2] * Wo[(size_t)k2*OUTD + c];
        logits[c] = acc;
    }
    __syncthreads();
    float m = -1e30f;
    for (int c = tid; c < OUTD; c += 256) m = fmaxf(m, logits[c]);
#pragma unroll
    for (int o = 16; o; o >>= 1) m = fmaxf(m, __shfl_xor_sync(0xffffffffu, m, o));
    if ((tid & 31) == 0) red[tid>>5] = m;
    __syncthreads();
    if (tid < 32) {
        float a = (tid < 8) ? red[tid] : -1e30f;
#pragma unroll
        for (int o = 4; o; o >>= 1) a = fmaxf(a, __shfl_xor_sync(0xffffffffu, a, o));
        if (tid == 0) red[0] = a;
    }
    __syncthreads();
    m = red[0];
    __syncthreads();
    float s = 0.f;
    for (int c = tid; c < OUTD; c += 256) { float e = expf(logits[c] - m); logits[c] = e; s += e; }
#pragma unroll
    for (int o = 16; o; o >>= 1) s += __shfl_xor_sync(0xffffffffu, s, o);
    if ((tid & 31) == 0) red[tid>>5] = s;
    __syncthreads();
    if (tid < 32) {
        float a = (tid < 8) ? red[tid] : 0.f;
#pragma unroll
        for (int o = 4; o; o >>= 1) a += __shfl_xor_sync(0xffffffffu, a, o);
        if (tid == 0) red[0] = a;
    }
    __syncthreads();
    float inv = 1.0f / red[0];
    for (int c = tid; c < OUTD; c += 256) res[(size_t)b*OUTD + c] = logits[c]*inv;
}

// ---------------- launch ----------------
extern "C" void kernel_launch(void* const* d_in, const int* in_sizes, int n_in,
                              void* d_out, int out_size) {
    const float* images = (const float*)d_in[0];
    const float* Wp     = (const float*)d_in[1];
    const float* bp     = (const float*)d_in[2];
    const float* cls    = (const float*)d_in[3];
    const float* ln1_g  = (const float*)d_in[4];
    const float* ln1_b  = (const float*)d_in[5];
    const float* Wq     = (const float*)d_in[6];
    const float* bq     = (const float*)d_in[7];
    const float* Wk     = (const float*)d_in[8];
    const float* bk     = (const float*)d_in[9];
    const float* Wv     = (const float*)d_in[10];
    const float* bv     = (const float*)d_in[11];
    const float* ln2_g  = (const float*)d_in[12];
    const float* ln2_b  = (const float*)d_in[13];
    const float* W1     = (const float*)d_in[14];
    const float* b1     = (const float*)d_in[15];
    const float* W2     = (const float*)d_in[16];
    const float* b2     = (const float*)d_in[17];
    const float* Wo     = (const float*)d_in[18];
    const float* bo     = (const float*)d_in[19];
    float* outp = (float*)d_out;

    float *p_out, *p_q, *p_k, *p_v, *p_att;
    __half *p_xh, *p_ffh, *p_wh;
    cudaGetSymbolAddress((void**)&p_out, g_out);
    cudaGetSymbolAddress((void**)&p_xh,  g_xh);
    cudaGetSymbolAddress((void**)&p_ffh, g_ffh);
    cudaGetSymbolAddress((void**)&p_q,   g_q);
    cudaGetSymbolAddress((void**)&p_k,   g_k);
    cudaGetSymbolAddress((void**)&p_v,   g_v);
    cudaGetSymbolAddress((void**)&p_att, g_att);
    cudaGetSymbolAddress((void**)&p_wh,  g_wh);

    const __half* hWp = p_wh;
    const __half* hW1 = p_wh + WPN;
    const __half* hW2 = p_wh + WPN + W1N;

    static bool attr_set = false;
    if (!attr_set) {
        cudaFuncSetAttribute(gemm_f16<0,0,0>, cudaFuncAttributeMaxDynamicSharedMemorySize, GEMM_SMEM_BYTES);
        cudaFuncSetAttribute(gemm_f16<1,0,1>, cudaFuncAttributeMaxDynamicSharedMemorySize, GEMM_SMEM_BYTES);
        cudaFuncSetAttribute(gemm_f16<0,1,0>, cudaFuncAttributeMaxDynamicSharedMemorySize, GEMM_SMEM_BYTES);
        attr_set = true;
    }

    // 0) convert weights to half
    convert_weights_kernel<<<(WTOT + 255)/256, 256>>>(Wp, W1, W2, p_wh);

    // 1) patchify (half) + patch embedding (fp32 out via g_q scratch)
    patchify_kernel<<<(BP*HID + 255)/256, 256>>>(images, p_xh);
    gemm_f16<0,0,0><<<dim3(HID/128, (BP+255)/256), 512, GEMM_SMEM_BYTES>>>(p_xh, hWp, bp, p_q, BP, HID, HID);
    add_pos_cls_kernel<<<(BS*HID + 255)/256, 256>>>(p_q, cls, p_out);

    // 2) transformer layers
    for (int l = 0; l < NL; l++) {
        ln_kernel<<<BS, 256>>>(p_out, ln1_g + l*HID, ln1_b + l*HID, p_xh);
        qkv_fused_kernel<<<dim3(BS/64, NH, 3), 256>>>(p_xh,
            Wq + (size_t)l*NH*DH*DH, bq + l*NH*DH, p_q,
            Wk + (size_t)l*NH*DH*DH, bk + l*NH*DH, p_k,
            Wv + (size_t)l*NH*DH*DH, bv + l*NH*DH, p_v);
        attn_score_kernel<<<dim3(7, BATCH*NH), 256>>>(p_q, p_k, p_att);
        attn_av_kernel<<<dim3(7, BATCH*NH), 256>>>(p_att, p_v, p_out);
        ln_kernel<<<BS, 256>>>(p_out, ln2_g + l*HID, ln2_b + l*HID, p_xh);
        gemm_f16<1,0,1><<<dim3(DFF/128, (BS+255)/256), 512, GEMM_SMEM_BYTES>>>(p_xh, hW1 + (size_t)l*HID*DFF, b1 + l*DFF, p_ffh, BS, DFF, HID);
        gemm_f16<0,1,0><<<dim3(HID/128, (BS+255)/256), 512, GEMM_SMEM_BYTES>>>(p_ffh, hW2 + (size_t)l*DFF*HID, b2 + l*HID, p_out, BS, HID, DFF);
    }

    // 3) classification head + softmax
    head_kernel<<<BATCH, 256>>>(p_out, Wo, bo, outp);
}

// round 14
// speedup vs baseline: 1.4926x; 1.4926x over previous
#include <cuda_runtime.h>
#include <cuda_fp16.h>
#include <math.h>
#include <stdint.h>

#define BATCH 64
#define SEQ 197
#define NPATCH 196
#define HID 768
#define NH 12
#define DH 64
#define DFF 3072
#define NL 4
#define OUTD 1000

#define BS (BATCH*SEQ)      // 12608
#define BP (BATCH*NPATCH)   // 12544

#define WPN (768*768)
#define W1N (NL*HID*DFF)
#define W2N (NL*DFF*HID)
#define WTOT (WPN + W1N + W2N)

// ---------------- scratch (static device globals; no allocations) ----------------
__device__ float  g_out[(size_t)BS*HID];
__device__ __half g_xh [(size_t)BS*HID];     // half activations (ln out / patches)
__device__ __half g_ffh[(size_t)BS*DFF];     // half FF1 output
__device__ float  g_q  [(size_t)BS*HID];     // fp32 scratch (patch embed out)
__device__ __half g_qh [(size_t)BS*HID];
__device__ __half g_kh [(size_t)BS*HID];
__device__ __half g_vh [(size_t)BS*HID];
__device__ __half g_wh [(size_t)WTOT];       // half weights {Wp, W1, W2}

// ---------------- weight convert ----------------
__global__ void convert_weights_kernel(const float* __restrict__ Wp,
                                       const float* __restrict__ W1,
                                       const float* __restrict__ W2,
                                       __half* __restrict__ dst) {
    size_t idx = (size_t)blockIdx.x * 256 + threadIdx.x;
    if (idx >= (size_t)WTOT) return;
    float v;
    if (idx < WPN)            v = Wp[idx];
    else if (idx < WPN + W1N) v = W1[idx - WPN];
    else                      v = W2[idx - WPN - W1N];
    dst[idx] = __float2half(v);
}

// ---------------- patchify -> half patches ----------------
__global__ void patchify_kernel(const float* __restrict__ img, __half* __restrict__ patches) {
    int idx = blockIdx.x * 256 + threadIdx.x;
    if (idx >= BP * HID) return;
    int k = idx % HID;
    int m = idx / HID;
    int b = m / NPATCH, p = m % NPATCH;
    int pr = p / 14, pc = p % 14;
    int c = k >> 8;
    int ij = k & 255;
    int i = ij >> 4, j = ij & 15;
    patches[idx] = __float2half(img[(((b*3 + c)*224) + pr*16 + i)*224 + pc*16 + j]);
}

__device__ __forceinline__ float gelu_exact(float x) {
    return 0.5f * x * (1.0f + erff(x * 0.7071067811865476f));
}

__device__ __forceinline__ void mma_f16(float c[4], uint32_t a0, uint32_t a1,
        uint32_t a2, uint32_t a3, uint32_t b0, uint32_t b1) {
    asm volatile(
        "mma.sync.aligned.m16n8k16.row.col.f32.f16.f16.f32 "
        "{%0,%1,%2,%3}, {%4,%5,%6,%7}, {%8,%9}, {%0,%1,%2,%3};"
        : "+f"(c[0]), "+f"(c[1]), "+f"(c[2]), "+f"(c[3])
        : "r"(a0), "r"(a1), "r"(a2), "r"(a3), "r"(b0), "r"(b1));
}

__device__ __forceinline__ void ldsm4(uint32_t r[4], uint32_t addr) {
    asm volatile("ldmatrix.sync.aligned.m8n8.x4.shared.b16 {%0,%1,%2,%3}, [%4];"
        : "=r"(r[0]), "=r"(r[1]), "=r"(r[2]), "=r"(r[3]) : "r"(addr));
}
__device__ __forceinline__ void ldsm4t(uint32_t r[4], uint32_t addr) {
    asm volatile("ldmatrix.sync.aligned.m8n8.x4.trans.shared.b16 {%0,%1,%2,%3}, [%4];"
        : "=r"(r[0]), "=r"(r[1]), "=r"(r[2]), "=r"(r[3]) : "r"(addr));
}

__device__ __forceinline__ void cp16(void* dst, const void* src) {
    uint32_t d = (uint32_t)__cvta_generic_to_shared(dst);
    asm volatile("cp.async.cg.shared.global [%0], [%1], 16;" :: "r"(d), "l"(src));
}
__device__ __forceinline__ void cp16s(uint32_t dst_shared, const void* src) {
    asm volatile("cp.async.cg.shared.global [%0], [%1], 16;" :: "r"(dst_shared), "l"(src));
}
__device__ __forceinline__ void cp_commit() { asm volatile("cp.async.commit_group;"); }
__device__ __forceinline__ void cp_wait1()  { asm volatile("cp.async.wait_group 1;"); }
__device__ __forceinline__ void cp_wait0()  { asm volatile("cp.async.wait_group 0;"); }

// ---------------- FP16 tensor-core GEMM (R9 config: 128x128, 256 thr) ----------
#define ASTR 40
#define BSTR 264
#define A_STAGE_H (128*ASTR)
#define B_STAGE_H (32*BSTR)
#define A_STAGE_B (A_STAGE_H*2)
#define B_STAGE_B (B_STAGE_H*2)
#define GEMM_SMEM_BYTES (3*(A_STAGE_B + B_STAGE_B))   // 81408

template<int ACT, int RESID, int OUTH>
__global__ void __launch_bounds__(256) gemm_f16(
        const __half* __restrict__ A, const __half* __restrict__ B,
        const float* __restrict__ bias, void* __restrict__ Cv,
        int M, int N, int K)
{
    extern __shared__ uint32_t smem_dyn[];
    __half* Ash = (__half*)smem_dyn;
    __half* Bsh = (__half*)smem_dyn + 3*A_STAGE_H;
    uint32_t s_base = (uint32_t)__cvta_generic_to_shared(smem_dyn);
    uint32_t a_s32 = s_base;
    uint32_t b_s32 = s_base + 3*A_STAGE_B;

    int tid  = threadIdx.x;
    int lane = tid & 31;
    int warp = tid >> 5;
    int warp_m = (warp >> 2) * 64;
    int warp_n = (warp & 3) * 32;
    int gid = lane >> 2, tig = lane & 3;

    int row0 = blockIdx.y * 128, col0 = blockIdx.x * 128;

    int rowA = tid >> 1;
    int akh  = (tid & 1) * 16;
    int arow = row0 + rowA; if (arow >= M) arow = M - 1;
    const __half* Aptr = A + (size_t)arow * K + akh;
    int rowB = tid >> 3;
    int nch  = (tid & 7) * 16;
    const __half* Bptr = B + (size_t)rowB * N + col0 + nch;

    uint32_t aoff = (uint32_t)((lane & 15) * (ASTR*2) + (lane >> 4) * 16);
    uint32_t boff = (uint32_t)((lane & 15) * (BSTR*2) + (lane >> 4) * 16);

    float acc[4][4][4];
#pragma unroll
    for (int i = 0; i < 4; i++)
#pragma unroll
        for (int j = 0; j < 4; j++)
#pragma unroll
            for (int r = 0; r < 4; r++) acc[i][j][r] = 0.f;

    int nt = K >> 5;

#pragma unroll
    for (int s = 0; s < 2; s++) {
        const __half* ap = Aptr + (size_t)s * 32;
        cp16(Ash + (size_t)s*A_STAGE_H + rowA*ASTR + akh,     ap);
        cp16(Ash + (size_t)s*A_STAGE_H + rowA*ASTR + akh + 8, ap + 8);
        const __half* bp = Bptr + (size_t)s * 32 * N;
        cp16(Bsh + (size_t)s*B_STAGE_H + rowB*BSTR + nch,     bp);
        cp16(Bsh + (size_t)s*B_STAGE_H + rowB*BSTR + nch + 8, bp + 8);
        cp_commit();
    }

    for (int t = 0; t < nt; t++) {
        cp_wait1();
        __syncthreads();
        int buf = t % 3;
        uint32_t abase = a_s32 + buf*A_STAGE_B + warp_m*(ASTR*2) + aoff;
        uint32_t bbase = b_s32 + buf*B_STAGE_B + warp_n*2 + boff;
#pragma unroll
        for (int k16 = 0; k16 < 2; k16++) {
            uint32_t ak = abase + k16*32;
            uint32_t bk = bbase + k16*16*(BSTR*2);
            uint32_t afr[4][4];
#pragma unroll
            for (int ma = 0; ma < 4; ma++)
                ldsm4(afr[ma], ak + ma*16*(ASTR*2));
            uint32_t bq[2][4];
#pragma unroll
            for (int nb = 0; nb < 2; nb++)
                ldsm4t(bq[nb], bk + nb*32);
#pragma unroll
            for (int ma = 0; ma < 4; ma++) {
#pragma unroll
                for (int nb = 0; nb < 2; nb++) {
                    mma_f16(acc[ma][nb*2],   afr[ma][0], afr[ma][1], afr[ma][2], afr[ma][3],
                            bq[nb][0], bq[nb][1]);
                    mma_f16(acc[ma][nb*2+1], afr[ma][0], afr[ma][1], afr[ma][2], afr[ma][3],
                            bq[nb][2], bq[nb][3]);
                }
            }
        }
        if (t + 2 < nt) {
            int s = (t + 2) % 3;
            const __half* ap = Aptr + (size_t)(t + 2) * 32;
            cp16(Ash + (size_t)s*A_STAGE_H + rowA*ASTR + akh,     ap);
            cp16(Ash + (size_t)s*A_STAGE_H + rowA*ASTR + akh + 8, ap + 8);
            const __half* bp = Bptr + (size_t)(t + 2) * 32 * N;
            cp16(Bsh + (size_t)s*B_STAGE_H + rowB*BSTR + nch,     bp);
            cp16(Bsh + (size_t)s*B_STAGE_H + rowB*BSTR + nch + 8, bp + 8);
        }
        cp_commit();
    }

#pragma unroll
    for (int ma = 0; ma < 4; ma++) {
        int r_lo = row0 + warp_m + ma * 16 + gid;
        int r_hi = r_lo + 8;
#pragma unroll
        for (int na = 0; na < 4; na++) {
            int c = col0 + warp_n + na * 8 + tig * 2;
            float bc0 = bias[c], bc1 = bias[c + 1];
            if (r_lo < M) {
                float v0 = acc[ma][na][0] + bc0;
                float v1 = acc[ma][na][1] + bc1;
                size_t off = (size_t)r_lo * N + c;
                if (ACT == 1) { v0 = gelu_exact(v0); v1 = gelu_exact(v1); }
                if (OUTH) {
                    *(__half2*)((__half*)Cv + off) = __floats2half2_rn(v0, v1);
                } else if (RESID) {
                    ((float*)Cv)[off] += v0; ((float*)Cv)[off + 1] += v1;
                } else {
                    ((float*)Cv)[off]  = v0; ((float*)Cv)[off + 1]  = v1;
                }
            }
            if (r_hi < M) {
                float v2 = acc[ma][na][2] + bc0;
                float v3 = acc[ma][na][3] + bc1;
                size_t off = (size_t)r_hi * N + c;
                if (ACT == 1) { v2 = gelu_exact(v2); v3 = gelu_exact(v3); }
                if (OUTH) {
                    *(__half2*)((__half*)Cv + off) = __floats2half2_rn(v2, v3);
                } else if (RESID) {
                    ((float*)Cv)[off] += v2; ((float*)Cv)[off + 1] += v3;
                } else {
                    ((float*)Cv)[off]  = v2; ((float*)Cv)[off + 1]  = v3;
                }
            }
        }
    }
}

// ---------------- fused attention: S=QK^T, softmax, O += P V ----------------
// grid (4, BATCH*NH), 256 thr. Per block: 64 q-rows, full 197 keys (padded 224).
// P stride = 232 halves (464B = 29x16B, conflict-free & covers 224 cols).
#define AT_Q_OFF 0
#define AT_K_OFF 9216
#define AT_V_OFF 41472
#define AT_S_OFF 73728
#define AT_P_OFF 128000
#define AT_PSTR  232
#define AT_SMEM  (AT_P_OFF + 64*AT_PSTR*2)   // 157696

__global__ void __launch_bounds__(256) attn_fused_kernel(
        const __half* __restrict__ qh, const __half* __restrict__ kh,
        const __half* __restrict__ vh, float* __restrict__ outp)
{
    extern __shared__ char smem[];
    uint32_t sb = (uint32_t)__cvta_generic_to_shared(smem);
    float* S32 = (float*)(smem + AT_S_OFF);
    __half* P  = (__half*)(smem + AT_P_OFF);

    int tid = threadIdx.x;
    int lane = tid & 31, warp = tid >> 5;
    int gid = lane >> 2, tig = lane & 3;
    int bh = blockIdx.y;
    int b = bh / NH, h = bh % NH;
    int q0 = blockIdx.x * 64;

    // ---- load Q (64 rows), K,V (224 rows, clamped) ----
#pragma unroll
    for (int i = 0; i < 2; i++) {
        int op = tid + i * 256;
        int row = op >> 3, c = op & 7;
        int grow = q0 + row; if (grow > SEQ - 1) grow = SEQ - 1;
        cp16s(sb + AT_Q_OFF + row*144 + c*16, qh + (size_t)(b*SEQ + grow)*HID + h*DH + c*8);
    }
#pragma unroll
    for (int i = 0; i < 7; i++) {
        int op = tid + i * 256;
        int row = op >> 3, c = op & 7;
        int grow = row > SEQ - 1 ? SEQ - 1 : row;
        const size_t goff = (size_t)(b*SEQ + grow)*HID + h*DH + c*8;
        cp16s(sb + AT_K_OFF + row*144 + c*16, kh + goff);
        cp16s(sb + AT_V_OFF + row*144 + c*16, vh + goff);
    }
    cp_commit();
    cp_wait0();
    __syncthreads();

    int mt = warp >> 1;          // 0..3  (16 q-rows each)
    int nh_ = warp & 1;          // 0/1   (half of key range)

    // ---- S = Q K^T ----
    float s_[7][2][4];
#pragma unroll
    for (int j = 0; j < 7; j++)
#pragma unroll
        for (int hf = 0; hf < 2; hf++)
#pragma unroll
            for (int r = 0; r < 4; r++) s_[j][hf][r] = 0.f;

#pragma unroll
    for (int k16 = 0; k16 < 4; k16++) {
        uint32_t afr[4];
        ldsm4(afr, sb + AT_Q_OFF + (mt*16 + (lane & 15))*144 + (lane >> 4)*16 + k16*32);
#pragma unroll
        for (int j = 0; j < 7; j++) {
            int g = nh_ * 7 + j;
            uint32_t kr[4];
            ldsm4(kr, sb + AT_K_OFF + (g*16 + (lane & 15))*144 + (lane >> 4)*16 + k16*32);
            // non-trans ldsm on [n][k]: b0=r0,b1=r2 (n0-7); b0=r1,b1=r3 (n8-15)
            mma_f16(s_[j][0], afr[0], afr[1], afr[2], afr[3], kr[0], kr[2]);
            mma_f16(s_[j][1], afr[0], afr[1], afr[2], afr[3], kr[1], kr[3]);
        }
    }
    // store scores (scaled)
#pragma unroll
    for (int j = 0; j < 7; j++)
#pragma unroll
        for (int hf = 0; hf < 2; hf++) {
            int col = (nh_*7 + j)*16 + hf*8 + tig*2;
            int r0 = mt*16 + gid;
            S32[r0*212 + col]       = s_[j][hf][0] * 0.125f;
            S32[r0*212 + col + 1]   = s_[j][hf][1] * 0.125f;
            S32[(r0+8)*212 + col]     = s_[j][hf][2] * 0.125f;
            S32[(r0+8)*212 + col + 1] = s_[j][hf][3] * 0.125f;
        }
    __syncthreads();

    // ---- softmax rows (warp w: rows w*8..w*8+7), write P half ----
    for (int rr = 0; rr < 8; rr++) {
        int row = warp*8 + rr;
        float m = -1e30f;
        for (int j = lane; j < SEQ; j += 32) m = fmaxf(m, S32[row*212 + j]);
#pragma unroll
        for (int o = 16; o; o >>= 1) m = fmaxf(m, __shfl_xor_sync(0xffffffffu, m, o));
        float ssum = 0.f;
        for (int j = lane; j < SEQ; j += 32) {
            float e = expf(S32[row*212 + j] - m);
            S32[row*212 + j] = e;
            ssum += e;
        }
#pragma unroll
        for (int o = 16; o; o >>= 1) ssum += __shfl_xor_sync(0xffffffffu, ssum, o);
        float inv = 1.0f / ssum;
        for (int j = lane; j < 224; j += 32)
            P[row*AT_PSTR + j] = (j < SEQ) ? __float2half(S32[row*212 + j] * inv)
                                           : __ushort_as_half((unsigned short)0);
    }
    __syncthreads();

    // ---- O = P V ----
    float o_[2][2][4];
#pragma unroll
    for (int g2 = 0; g2 < 2; g2++)
#pragma unroll
        for (int m2 = 0; m2 < 2; m2++)
#pragma unroll
            for (int r = 0; r < 4; r++) o_[g2][m2][r] = 0.f;

#pragma unroll
    for (int k16 = 0; k16 < 14; k16++) {
        uint32_t pfr[4];
        ldsm4(pfr, sb + AT_P_OFF + (mt*16 + (lane & 15))*(AT_PSTR*2) + (lane >> 4)*16 + k16*32);
#pragma unroll
        for (int g2 = 0; g2 < 2; g2++) {
            uint32_t vr[4];
            ldsm4t(vr, sb + AT_V_OFF + (k16*16 + (lane & 15))*144 + (lane >> 4)*16 + (nh_*32 + g2*16)*2);
            mma_f16(o_[g2][0], pfr[0], pfr[1], pfr[2], pfr[3], vr[0], vr[1]);
            mma_f16(o_[g2][1], pfr[0], pfr[1], pfr[2], pfr[3], vr[2], vr[3]);
        }
    }
    // write += to residual
#pragma unroll
    for (int g2 = 0; g2 < 2; g2++)
#pragma unroll
        for (int m2 = 0; m2 < 2; m2++) {
            int col = h*DH + nh_*32 + g2*16 + m2*8 + tig*2;
            int r_lo = q0 + mt*16 + gid;
            int r_hi = r_lo + 8;
            if (r_lo < SEQ) {
                size_t off = (size_t)(b*SEQ + r_lo)*HID + col;
                outp[off]     += o_[g2][m2][0];
                outp[off + 1] += o_[g2][m2][1];
            }
            if (r_hi < SEQ) {
                size_t off = (size_t)(b*SEQ + r_hi)*HID + col;
                outp[off]     += o_[g2][m2][2];
                outp[off + 1] += o_[g2][m2][3];
            }
        }
}

// ---------------- pos-emb + cls assembly ----------------
__global__ void add_pos_cls_kernel(const float* __restrict__ tok,
                                   const float* __restrict__ cls,
                                   float* __restrict__ outp) {
    int idx = blockIdx.x * 256 + threadIdx.x;
    if (idx >= BS * HID) return;
    int d = idx % HID;
    int r = idx / HID;
    int b = r / SEQ, s = r % SEQ;
    float jf = (float)((d >> 1) << 1);
    float denom = powf(10000.0f, jf * (1.0f/768.0f));
    float ang = (float)s / denom;
    float pos = (d & 1) ? cosf(ang) : sinf(ang);
    float base = (s == 0) ? cls[d] : tok[(size_t)(b*NPATCH + s - 1)*HID + d];
    outp[idx] = base + pos;
}

// ---------------- LayerNorm -> half output ----------------
__global__ void __launch_bounds__(256) ln_kernel(const float* __restrict__ in,
        const float* __restrict__ gam, const float* __restrict__ bet,
        __half* __restrict__ outp) {
    __shared__ float red[16];
    int row = blockIdx.x;
    int tid = threadIdx.x;
    const float* x = in + (size_t)row * HID;
    float v0 = x[tid], v1 = x[tid+256], v2 = x[tid+512];
    float s  = v0 + v1 + v2;
    float ss = v0*v0 + v1*v1 + v2*v2;
#pragma unroll
    for (int o = 16; o; o >>= 1) {
        s  += __shfl_xor_sync(0xffffffffu, s, o);
        ss += __shfl_xor_sync(0xffffffffu, ss, o);
    }
    if ((tid & 31) == 0) { red[tid>>5] = s; red[8 + (tid>>5)] = ss; }
    __syncthreads();
    if (tid < 32) {
        float a  = (tid < 8) ? red[tid]   : 0.f;
        float bb = (tid < 8) ? red[8+tid] : 0.f;
#pragma unroll
        for (int o = 4; o; o >>= 1) {
            a  += __shfl_xor_sync(0xffffffffu, a, o);
            bb += __shfl_xor_sync(0xffffffffu, bb, o);
        }
        if (tid == 0) { red[0] = a; red[1] = bb; }
    }
    __syncthreads();
    float mean = red[0] * (1.0f/768.0f);
    float var  = red[1] * (1.0f/768.0f) - mean*mean;
    float rstd = rsqrtf(var + 1e-5f);
    __half* o = outp + (size_t)row * HID;
    o[tid]     = __float2half((v0 - mean)*rstd*gam[tid]     + bet[tid]);
    o[tid+256] = __float2half((v1 - mean)*rstd*gam[tid+256] + bet[tid+256]);
    o[tid+512] = __float2half((v2 - mean)*rstd*gam[tid+512] + bet[tid+512]);
}

// ---------------- fused QKV per-head projection (half x, fp32 W, half out) ----
__global__ void __launch_bounds__(256) qkv_fused_kernel(const __half* __restrict__ x,
        const float* __restrict__ Wq, const float* __restrict__ bq, __half* __restrict__ oq,
        const float* __restrict__ Wk, const float* __restrict__ bk, __half* __restrict__ ok,
        const float* __restrict__ Wv, const float* __restrict__ bv, __half* __restrict__ ov) {
    const float* W; const float* bias; __half* outp;
    if (blockIdx.z == 0)      { W = Wq; bias = bq; outp = oq; }
    else if (blockIdx.z == 1) { W = Wk; bias = bk; outp = ok; }
    else                      { W = Wv; bias = bv; outp = ov; }

    __shared__ __align__(16) float Xs[DH][68];
    __shared__ __align__(16) float Ws[DH][68];
    int h = blockIdx.y;
    int row0 = blockIdx.x * 64;
    int tid = threadIdx.x;
    {
        int r  = tid >> 2;
        int d0 = (tid & 3) * 16;
        const __half* src = x + (size_t)(row0 + r)*HID + h*DH + d0;
        const float* wsrc = W + (size_t)h*DH*DH + (size_t)r*DH + d0;
#pragma unroll
        for (int q8 = 0; q8 < 2; q8++) {
            uint4 u = *(const uint4*)(src + q8*8);
#pragma unroll
            for (int j = 0; j < 4; j++) {
                __half2 h2 = ((const __half2*)&u)[j];
                float2 f2 = __half22float2(h2);
                Xs[d0 + q8*8 + j*2    ][r] = f2.x;
                Xs[d0 + q8*8 + j*2 + 1][r] = f2.y;
            }
        }
#pragma unroll
        for (int u2 = 0; u2 < 4; u2++) {
            float4 w = *(const float4*)(wsrc + u2*4);
            Ws[d0+u2*4+0][r]=w.x; Ws[d0+u2*4+1][r]=w.y; Ws[d0+u2*4+2][r]=w.z; Ws[d0+u2*4+3][r]=w.w;
        }
    }
    __syncthreads();
    int tr = (tid >> 4) * 4;
    int tc = (tid & 15) * 4;
    float acc[4][4] = {{0.f}};
#pragma unroll
    for (int d = 0; d < DH; d++) {
        float4 av = *(const float4*)&Xs[d][tr];
        float4 bv4 = *(const float4*)&Ws[d][tc];
        acc[0][0] += av.x*bv4.x; acc[0][1] += av.x*bv4.y; acc[0][2] += av.x*bv4.z; acc[0][3] += av.x*bv4.w;
        acc[1][0] += av.y*bv4.x; acc[1][1] += av.y*bv4.y; acc[1][2] += av.y*bv4.z; acc[1][3] += av.y*bv4.w;
        acc[2][0] += av.z*bv4.x; acc[2][1] += av.z*bv4.y; acc[2][2] += av.z*bv4.z; acc[2][3] += av.z*bv4.w;
        acc[3][0] += av.w*bv4.x; acc[3][1] += av.w*bv4.y; acc[3][2] += av.w*bv4.z; acc[3][3] += av.w*bv4.w;
    }
#pragma unroll
    for (int i = 0; i < 4; i++) {
        __half* dst = outp + (size_t)(row0 + tr + i)*HID + h*DH + tc;
#pragma unroll
        for (int j = 0; j < 4; j++) dst[j] = __float2half(acc[i][j] + bias[h*DH + tc + j]);
    }
}

// ---------------- head ----------------
__global__ void __launch_bounds__(256) head_kernel(const float* __restrict__ xin,
        const float* __restrict__ Wo, const float* __restrict__ bo,
        float* __restrict__ res) {
    __shared__ float xs[HID];
    __shared__ float logits[OUTD];
    __shared__ float red[8];
    int b = blockIdx.x;
    int tid = threadIdx.x;
    const float* src = xin + (size_t)b*SEQ*HID;
    xs[tid] = src[tid]; xs[tid+256] = src[tid+256]; xs[tid+512] = src[tid+512];
    __syncthreads();
    for (int c = tid; c < OUTD; c += 256) {
        float acc = bo[c];
#pragma unroll 8
        for (int k2 = 0; k2 < HID; k2++) acc += xs[k2] * Wo[(size_t)k2*OUTD + c];
        logits[c] = acc;
    }
    __syncthreads();
    float m = -1e30f;
    for (int c = tid; c < OUTD; c += 256) m = fmaxf(m, logits[c]);
#pragma unroll
    for (int o = 16; o; o >>= 1) m = fmaxf(m, __shfl_xor_sync(0xffffffffu, m, o));
    if ((tid & 31) == 0) red[tid>>5] = m;
    __syncthreads();
    if (tid < 32) {
        float a = (tid < 8) ? red[tid] : -1e30f;
#pragma unroll
        for (int o = 4; o; o >>= 1) a = fmaxf(a, __shfl_xor_sync(0xffffffffu, a, o));
        if (tid == 0) red[0] = a;
    }
    __syncthreads();
    m = red[0];
    __syncthreads();
    float s = 0.f;
    for (int c = tid; c < OUTD; c += 256) { float e = expf(logits[c] - m); logits[c] = e; s += e; }
#pragma unroll
    for (int o = 16; o; o >>= 1) s += __shfl_xor_sync(0xffffffffu, s, o);
    if ((tid & 31) == 0) red[tid>>5] = s;
    __syncthreads();
    if (tid < 32) {
        float a = (tid < 8) ? red[tid] : 0.f;
#pragma unroll
        for (int o = 4; o; o >>= 1) a += __shfl_xor_sync(0xffffffffu, a, o);
        if (tid == 0) red[0] = a;
    }
    __syncthreads();
    float inv = 1.0f / red[0];
    for (int c = tid; c < OUTD; c += 256) res[(size_t)b*OUTD + c] = logits[c]*inv;
}

// ---------------- launch ----------------
extern "C" void kernel_launch(void* const* d_in, const int* in_sizes, int n_in,
                              void* d_out, int out_size) {
    const float* images = (const float*)d_in[0];
    const float* Wp     = (const float*)d_in[1];
    const float* bp     = (const float*)d_in[2];
    const float* cls    = (const float*)d_in[3];
    const float* ln1_g  = (const float*)d_in[4];
    const float* ln1_b  = (const float*)d_in[5];
    const float* Wq     = (const float*)d_in[6];
    const float* bq     = (const float*)d_in[7];
    const float* Wk     = (const float*)d_in[8];
    const float* bk     = (const float*)d_in[9];
    const float* Wv     = (const float*)d_in[10];
    const float* bv     = (const float*)d_in[11];
    const float* ln2_g  = (const float*)d_in[12];
    const float* ln2_b  = (const float*)d_in[13];
    const float* W1     = (const float*)d_in[14];
    const float* b1     = (const float*)d_in[15];
    const float* W2     = (const float*)d_in[16];
    const float* b2     = (const float*)d_in[17];
    const float* Wo     = (const float*)d_in[18];
    const float* bo     = (const float*)d_in[19];
    float* outp = (float*)d_out;

    float *p_out, *p_q;
    __half *p_xh, *p_ffh, *p_wh, *p_qh, *p_kh, *p_vh;
    cudaGetSymbolAddress((void**)&p_out, g_out);
    cudaGetSymbolAddress((void**)&p_xh,  g_xh);
    cudaGetSymbolAddress((void**)&p_ffh, g_ffh);
    cudaGetSymbolAddress((void**)&p_q,   g_q);
    cudaGetSymbolAddress((void**)&p_qh,  g_qh);
    cudaGetSymbolAddress((void**)&p_kh,  g_kh);
    cudaGetSymbolAddress((void**)&p_vh,  g_vh);
    cudaGetSymbolAddress((void**)&p_wh,  g_wh);

    const __half* hWp = p_wh;
    const __half* hW1 = p_wh + WPN;
    const __half* hW2 = p_wh + WPN + W1N;

    static bool attr_set = false;
    if (!attr_set) {
        cudaFuncSetAttribute(gemm_f16<0,0,0>, cudaFuncAttributeMaxDynamicSharedMemorySize, GEMM_SMEM_BYTES);
        cudaFuncSetAttribute(gemm_f16<1,0,1>, cudaFuncAttributeMaxDynamicSharedMemorySize, GEMM_SMEM_BYTES);
        cudaFuncSetAttribute(gemm_f16<0,1,0>, cudaFuncAttributeMaxDynamicSharedMemorySize, GEMM_SMEM_BYTES);
        cudaFuncSetAttribute(attn_fused_kernel, cudaFuncAttributeMaxDynamicSharedMemorySize, AT_SMEM);
        attr_set = true;
    }

    // 0) convert weights to half
    convert_weights_kernel<<<(WTOT + 255)/256, 256>>>(Wp, W1, W2, p_wh);

    // 1) patchify + patch embedding
    patchify_kernel<<<(BP*HID + 255)/256, 256>>>(images, p_xh);
    gemm_f16<0,0,0><<<dim3(HID/128, (BP+127)/128), 256, GEMM_SMEM_BYTES>>>(p_xh, hWp, bp, p_q, BP, HID, HID);
    add_pos_cls_kernel<<<(BS*HID + 255)/256, 256>>>(p_q, cls, p_out);

    // 2) transformer layers
    for (int l = 0; l < NL; l++) {
        ln_kernel<<<BS, 256>>>(p_out, ln1_g + l*HID, ln1_b + l*HID, p_xh);
        qkv_fused_kernel<<<dim3(BS/64, NH, 3), 256>>>(p_xh,
            Wq + (size_t)l*NH*DH*DH, bq + l*NH*DH, p_qh,
            Wk + (size_t)l*NH*DH*DH, bk + l*NH*DH, p_kh,
            Wv + (size_t)l*NH*DH*DH, bv + l*NH*DH, p_vh);
        attn_fused_kernel<<<dim3(4, BATCH*NH), 256, AT_SMEM>>>(p_qh, p_kh, p_vh, p_out);
        ln_kernel<<<BS, 256>>>(p_out, ln2_g + l*HID, ln2_b + l*HID, p_xh);
        gemm_f16<1,0,1><<<dim3(DFF/128, (BS+127)/128), 256, GEMM_SMEM_BYTES>>>(p_xh, hW1 + (size_t)l*HID*DFF, b1 + l*DFF, p_ffh, BS, DFF, HID);
        gemm_f16<0,1,0><<<dim3(HID/128, (BS+127)/128), 256, GEMM_SMEM_BYTES>>>(p_ffh, hW2 + (size_t)l*DFF*HID, b2 + l*HID, p_out, BS, HID, DFF);
    }

    // 3) classification head + softmax
    head_kernel<<<BATCH, 256>>>(p_out, Wo, bo, outp);
}

// round 15
// speedup vs baseline: 1.6263x; 1.0896x over previous
#include <cuda_runtime.h>
#include <cuda_fp16.h>
#include <math.h>
#include <stdint.h>

#define BATCH 64
#define SEQ 197
#define NPATCH 196
#define HID 768
#define NH 12
#define DH 64
#define DFF 3072
#define NL 4
#define OUTD 1000

#define BS (BATCH*SEQ)      // 12608
#define BP (BATCH*NPATCH)   // 12544

#define WPN (768*768)
#define W1N (NL*HID*DFF)
#define W2N (NL*DFF*HID)
#define WQN (NL*NH*DH*DH)
#define WTOT (WPN + W1N + W2N + 3*WQN)

// ---------------- scratch (static device globals; no allocations) ----------------
__device__ float  g_out[(size_t)BS*HID];
__device__ __half g_xh [(size_t)BS*HID];     // half activations (ln out / patches)
__device__ __half g_ffh[(size_t)BS*DFF];     // half FF1 output
__device__ float  g_q  [(size_t)BS*HID];     // fp32 scratch (patch embed out)
__device__ __half g_qh [(size_t)BS*HID];
__device__ __half g_kh [(size_t)BS*HID];
__device__ __half g_vh [(size_t)BS*HID];
__device__ __half g_wh [(size_t)WTOT];       // half weights {Wp, W1, W2, Wq, Wk, Wv}

// ---------------- weight convert ----------------
__global__ void convert_weights_kernel(const float* __restrict__ Wp,
                                       const float* __restrict__ W1,
                                       const float* __restrict__ W2,
                                       const float* __restrict__ Wq,
                                       const float* __restrict__ Wk,
                                       const float* __restrict__ Wv,
                                       __half* __restrict__ dst) {
    size_t idx = (size_t)blockIdx.x * 256 + threadIdx.x;
    if (idx >= (size_t)WTOT) return;
    float v;
    if (idx < WPN)                       v = Wp[idx];
    else if (idx < (size_t)WPN + W1N)    v = W1[idx - WPN];
    else if (idx < (size_t)WPN + W1N + W2N) v = W2[idx - WPN - W1N];
    else {
        size_t rel = idx - WPN - W1N - W2N;
        size_t z = rel / WQN, r = rel % WQN;
        v = (z == 0) ? Wq[r] : (z == 1) ? Wk[r] : Wv[r];
    }
    dst[idx] = __float2half(v);
}

// ---------------- patchify -> half patches ----------------
__global__ void patchify_kernel(const float* __restrict__ img, __half* __restrict__ patches) {
    int idx = blockIdx.x * 256 + threadIdx.x;
    if (idx >= BP * HID) return;
    int k = idx % HID;
    int m = idx / HID;
    int b = m / NPATCH, p = m % NPATCH;
    int pr = p / 14, pc = p % 14;
    int c = k >> 8;
    int ij = k & 255;
    int i = ij >> 4, j = ij & 15;
    patches[idx] = __float2half(img[(((b*3 + c)*224) + pr*16 + i)*224 + pc*16 + j]);
}

__device__ __forceinline__ float gelu_exact(float x) {
    return 0.5f * x * (1.0f + erff(x * 0.7071067811865476f));
}

__device__ __forceinline__ void mma_f16(float c[4], uint32_t a0, uint32_t a1,
        uint32_t a2, uint32_t a3, uint32_t b0, uint32_t b1) {
    asm volatile(
        "mma.sync.aligned.m16n8k16.row.col.f32.f16.f16.f32 "
        "{%0,%1,%2,%3}, {%4,%5,%6,%7}, {%8,%9}, {%0,%1,%2,%3};"
        : "+f"(c[0]), "+f"(c[1]), "+f"(c[2]), "+f"(c[3])
        : "r"(a0), "r"(a1), "r"(a2), "r"(a3), "r"(b0), "r"(b1));
}

__device__ __forceinline__ void ldsm4(uint32_t r[4], uint32_t addr) {
    asm volatile("ldmatrix.sync.aligned.m8n8.x4.shared.b16 {%0,%1,%2,%3}, [%4];"
        : "=r"(r[0]), "=r"(r[1]), "=r"(r[2]), "=r"(r[3]) : "r"(addr));
}
__device__ __forceinline__ void ldsm4t(uint32_t r[4], uint32_t addr) {
    asm volatile("ldmatrix.sync.aligned.m8n8.x4.trans.shared.b16 {%0,%1,%2,%3}, [%4];"
        : "=r"(r[0]), "=r"(r[1]), "=r"(r[2]), "=r"(r[3]) : "r"(addr));
}

__device__ __forceinline__ void cp16(void* dst, const void* src) {
    uint32_t d = (uint32_t)__cvta_generic_to_shared(dst);
    asm volatile("cp.async.cg.shared.global [%0], [%1], 16;" :: "r"(d), "l"(src));
}
__device__ __forceinline__ void cp16s(uint32_t dst_shared, const void* src) {
    asm volatile("cp.async.cg.shared.global [%0], [%1], 16;" :: "r"(dst_shared), "l"(src));
}
__device__ __forceinline__ void cp_commit() { asm volatile("cp.async.commit_group;"); }
__device__ __forceinline__ void cp_wait1()  { asm volatile("cp.async.wait_group 1;"); }
__device__ __forceinline__ void cp_wait0()  { asm volatile("cp.async.wait_group 0;"); }

// ---------------- FP16 tensor-core GEMM (128x128, 256 thr, 3-stage) ----------
#define ASTR 40
#define BSTR 264
#define A_STAGE_H (128*ASTR)
#define B_STAGE_H (32*BSTR)
#define A_STAGE_B (A_STAGE_H*2)
#define B_STAGE_B (B_STAGE_H*2)
#define GEMM_SMEM_BYTES (3*(A_STAGE_B + B_STAGE_B))   // 81408

template<int ACT, int RESID, int OUTH>
__global__ void __launch_bounds__(256) gemm_f16(
        const __half* __restrict__ A, const __half* __restrict__ B,
        const float* __restrict__ bias, void* __restrict__ Cv,
        int M, int N, int K)
{
    extern __shared__ uint32_t smem_dyn[];
    __half* Ash = (__half*)smem_dyn;
    __half* Bsh = (__half*)smem_dyn + 3*A_STAGE_H;
    uint32_t s_base = (uint32_t)__cvta_generic_to_shared(smem_dyn);
    uint32_t a_s32 = s_base;
    uint32_t b_s32 = s_base + 3*A_STAGE_B;

    int tid  = threadIdx.x;
    int lane = tid & 31;
    int warp = tid >> 5;
    int warp_m = (warp >> 2) * 64;
    int warp_n = (warp & 3) * 32;
    int gid = lane >> 2, tig = lane & 3;

    int row0 = blockIdx.y * 128, col0 = blockIdx.x * 128;

    int rowA = tid >> 1;
    int akh  = (tid & 1) * 16;
    int arow = row0 + rowA; if (arow >= M) arow = M - 1;
    const __half* Aptr = A + (size_t)arow * K + akh;
    int rowB = tid >> 3;
    int nch  = (tid & 7) * 16;
    const __half* Bptr = B + (size_t)rowB * N + col0 + nch;

    uint32_t aoff = (uint32_t)((lane & 15) * (ASTR*2) + (lane >> 4) * 16);
    uint32_t boff = (uint32_t)((lane & 15) * (BSTR*2) + (lane >> 4) * 16);

    float acc[4][4][4];
#pragma unroll
    for (int i = 0; i < 4; i++)
#pragma unroll
        for (int j = 0; j < 4; j++)
#pragma unroll
            for (int r = 0; r < 4; r++) acc[i][j][r] = 0.f;

    int nt = K >> 5;

#pragma unroll
    for (int s = 0; s < 2; s++) {
        const __half* ap = Aptr + (size_t)s * 32;
        cp16(Ash + (size_t)s*A_STAGE_H + rowA*ASTR + akh,     ap);
        cp16(Ash + (size_t)s*A_STAGE_H + rowA*ASTR + akh + 8, ap + 8);
        const __half* bp = Bptr + (size_t)s * 32 * N;
        cp16(Bsh + (size_t)s*B_STAGE_H + rowB*BSTR + nch,     bp);
        cp16(Bsh + (size_t)s*B_STAGE_H + rowB*BSTR + nch + 8, bp + 8);
        cp_commit();
    }

    for (int t = 0; t < nt; t++) {
        cp_wait1();
        __syncthreads();
        int buf = t % 3;
        uint32_t abase = a_s32 + buf*A_STAGE_B + warp_m*(ASTR*2) + aoff;
        uint32_t bbase = b_s32 + buf*B_STAGE_B + warp_n*2 + boff;
#pragma unroll
        for (int k16 = 0; k16 < 2; k16++) {
            uint32_t ak = abase + k16*32;
            uint32_t bk = bbase + k16*16*(BSTR*2);
            uint32_t afr[4][4];
#pragma unroll
            for (int ma = 0; ma < 4; ma++)
                ldsm4(afr[ma], ak + ma*16*(ASTR*2));
            uint32_t bq[2][4];
#pragma unroll
            for (int nb = 0; nb < 2; nb++)
                ldsm4t(bq[nb], bk + nb*32);
#pragma unroll
            for (int ma = 0; ma < 4; ma++) {
#pragma unroll
                for (int nb = 0; nb < 2; nb++) {
                    mma_f16(acc[ma][nb*2],   afr[ma][0], afr[ma][1], afr[ma][2], afr[ma][3],
                            bq[nb][0], bq[nb][1]);
                    mma_f16(acc[ma][nb*2+1], afr[ma][0], afr[ma][1], afr[ma][2], afr[ma][3],
                            bq[nb][2], bq[nb][3]);
                }
            }
        }
        if (t + 2 < nt) {
            int s = (t + 2) % 3;
            const __half* ap = Aptr + (size_t)(t + 2) * 32;
            cp16(Ash + (size_t)s*A_STAGE_H + rowA*ASTR + akh,     ap);
            cp16(Ash + (size_t)s*A_STAGE_H + rowA*ASTR + akh + 8, ap + 8);
            const __half* bp = Bptr + (size_t)(t + 2) * 32 * N;
            cp16(Bsh + (size_t)s*B_STAGE_H + rowB*BSTR + nch,     bp);
            cp16(Bsh + (size_t)s*B_STAGE_H + rowB*BSTR + nch + 8, bp + 8);
        }
        cp_commit();
    }

#pragma unroll
    for (int ma = 0; ma < 4; ma++) {
        int r_lo = row0 + warp_m + ma * 16 + gid;
        int r_hi = r_lo + 8;
#pragma unroll
        for (int na = 0; na < 4; na++) {
            int c = col0 + warp_n + na * 8 + tig * 2;
            float bc0 = bias[c], bc1 = bias[c + 1];
            if (r_lo < M) {
                float v0 = acc[ma][na][0] + bc0;
                float v1 = acc[ma][na][1] + bc1;
                size_t off = (size_t)r_lo * N + c;
                if (ACT == 1) { v0 = gelu_exact(v0); v1 = gelu_exact(v1); }
                if (OUTH) {
                    *(__half2*)((__half*)Cv + off) = __floats2half2_rn(v0, v1);
                } else if (RESID) {
                    ((float*)Cv)[off] += v0; ((float*)Cv)[off + 1] += v1;
                } else {
                    ((float*)Cv)[off]  = v0; ((float*)Cv)[off + 1]  = v1;
                }
            }
            if (r_hi < M) {
                float v2 = acc[ma][na][2] + bc0;
                float v3 = acc[ma][na][3] + bc1;
                size_t off = (size_t)r_hi * N + c;
                if (ACT == 1) { v2 = gelu_exact(v2); v3 = gelu_exact(v3); }
                if (OUTH) {
                    *(__half2*)((__half*)Cv + off) = __floats2half2_rn(v2, v3);
                } else if (RESID) {
                    ((float*)Cv)[off] += v2; ((float*)Cv)[off + 1] += v3;
                } else {
                    ((float*)Cv)[off]  = v2; ((float*)Cv)[off + 1]  = v3;
                }
            }
        }
    }
}

// ---------------- QKV via tensor cores: per-head 128x64x64 mma ----------------
// grid (ceil(BS/128), NH, 3), 256 thr (8 warps x 16 rows).
__global__ void __launch_bounds__(256) qkv_mma_kernel(const __half* __restrict__ x,
        const __half* __restrict__ Wq, const float* __restrict__ bq, __half* __restrict__ oq,
        const __half* __restrict__ Wk, const float* __restrict__ bk, __half* __restrict__ ok,
        const __half* __restrict__ Wv, const float* __restrict__ bv, __half* __restrict__ ov) {
    const __half* W; const float* bias; __half* outp;
    if (blockIdx.z == 0)      { W = Wq; bias = bq; outp = oq; }
    else if (blockIdx.z == 1) { W = Wk; bias = bk; outp = ok; }
    else                      { W = Wv; bias = bv; outp = ov; }

    __shared__ __align__(16) __half Xs[128][72];   // stride 144B = 9x16B
    __shared__ __align__(16) __half Ws[64][72];
    uint32_t xs32 = (uint32_t)__cvta_generic_to_shared(Xs);
    uint32_t ws32 = (uint32_t)__cvta_generic_to_shared(Ws);

    int tid = threadIdx.x;
    int lane = tid & 31, warp = tid >> 5;
    int gid = lane >> 2, tig = lane & 3;
    int h = blockIdx.y;
    int row0 = blockIdx.x * 128;

    // load x slice [128 x 64] and W[h] [64 x 64] (rows e, cols d)
#pragma unroll
    for (int i = 0; i < 4; i++) {
        int op = tid + i * 256;
        int row = op >> 3, c = op & 7;
        int grow = row0 + row; if (grow >= BS) grow = BS - 1;
        cp16s(xs32 + row*144 + c*16, x + (size_t)grow*HID + h*DH + c*8);
    }
#pragma unroll
    for (int i = 0; i < 2; i++) {
        int op = tid + i * 256;
        int row = op >> 3, c = op & 7;
        cp16s(ws32 + row*144 + c*16, W + (size_t)h*DH*DH + row*DH + c*8);
    }
    cp_commit();
    cp_wait0();
    __syncthreads();

    float acc[4][2][4];
#pragma unroll
    for (int g = 0; g < 4; g++)
#pragma unroll
        for (int hf = 0; hf < 2; hf++)
#pragma unroll
            for (int r = 0; r < 4; r++) acc[g][hf][r] = 0.f;

#pragma unroll
    for (int k16 = 0; k16 < 4; k16++) {
        uint32_t afr[4];
        ldsm4(afr, xs32 + (warp*16 + (lane & 15))*144 + (lane >> 4)*16 + k16*32);
#pragma unroll
        for (int g = 0; g < 4; g++) {
            uint32_t kr[4];
            ldsm4(kr, ws32 + (g*16 + (lane & 15))*144 + (lane >> 4)*16 + k16*32);
            mma_f16(acc[g][0], afr[0], afr[1], afr[2], afr[3], kr[0], kr[2]);
            mma_f16(acc[g][1], afr[0], afr[1], afr[2], afr[3], kr[1], kr[3]);
        }
    }

    int r_lo = row0 + warp*16 + gid;
    int r_hi = r_lo + 8;
#pragma unroll
    for (int g = 0; g < 4; g++)
#pragma unroll
        for (int hf = 0; hf < 2; hf++) {
            int e = g*16 + hf*8 + tig*2;
            float bc0 = bias[h*DH + e], bc1 = bias[h*DH + e + 1];
            if (r_lo < BS)
                *(__half2*)(outp + (size_t)r_lo*HID + h*DH + e) =
                    __floats2half2_rn(acc[g][hf][0] + bc0, acc[g][hf][1] + bc1);
            if (r_hi < BS)
                *(__half2*)(outp + (size_t)r_hi*HID + h*DH + e) =
                    __floats2half2_rn(acc[g][hf][2] + bc0, acc[g][hf][3] + bc1);
        }
}

// ---------------- fused attention: S=QK^T, softmax, O += P V ----------------
#define AT_Q_OFF 0
#define AT_K_OFF 9216
#define AT_V_OFF 41472
#define AT_S_OFF 73728
#define AT_P_OFF 128000
#define AT_PSTR  232
#define AT_SMEM  (AT_P_OFF + 64*AT_PSTR*2)   // 157696

__global__ void __launch_bounds__(256) attn_fused_kernel(
        const __half* __restrict__ qh, const __half* __restrict__ kh,
        const __half* __restrict__ vh, float* __restrict__ outp)
{
    extern __shared__ char smem[];
    uint32_t sb = (uint32_t)__cvta_generic_to_shared(smem);
    float* S32 = (float*)(smem + AT_S_OFF);
    __half* P  = (__half*)(smem + AT_P_OFF);

    int tid = threadIdx.x;
    int lane = tid & 31, warp = tid >> 5;
    int gid = lane >> 2, tig = lane & 3;
    int bh = blockIdx.y;
    int b = bh / NH, h = bh % NH;
    int q0 = blockIdx.x * 64;

#pragma unroll
    for (int i = 0; i < 2; i++) {
        int op = tid + i * 256;
        int row = op >> 3, c = op & 7;
        int grow = q0 + row; if (grow > SEQ - 1) grow = SEQ - 1;
        cp16s(sb + AT_Q_OFF + row*144 + c*16, qh + (size_t)(b*SEQ + grow)*HID + h*DH + c*8);
    }
#pragma unroll
    for (int i = 0; i < 7; i++) {
        int op = tid + i * 256;
        int row = op >> 3, c = op & 7;
        int grow = row > SEQ - 1 ? SEQ - 1 : row;
        const size_t goff = (size_t)(b*SEQ + grow)*HID + h*DH + c*8;
        cp16s(sb + AT_K_OFF + row*144 + c*16, kh + goff);
        cp16s(sb + AT_V_OFF + row*144 + c*16, vh + goff);
    }
    cp_commit();
    cp_wait0();
    __syncthreads();

    int mt = warp >> 1;
    int nh_ = warp & 1;

    float s_[7][2][4];
#pragma unroll
    for (int j = 0; j < 7; j++)
#pragma unroll
        for (int hf = 0; hf < 2; hf++)
#pragma unroll
            for (int r = 0; r < 4; r++) s_[j][hf][r] = 0.f;

#pragma unroll
    for (int k16 = 0; k16 < 4; k16++) {
        uint32_t afr[4];
        ldsm4(afr, sb + AT_Q_OFF + (mt*16 + (lane & 15))*144 + (lane >> 4)*16 + k16*32);
#pragma unroll
        for (int j = 0; j < 7; j++) {
            int g = nh_ * 7 + j;
            uint32_t kr[4];
            ldsm4(kr, sb + AT_K_OFF + (g*16 + (lane & 15))*144 + (lane >> 4)*16 + k16*32);
            mma_f16(s_[j][0], afr[0], afr[1], afr[2], afr[3], kr[0], kr[2]);
            mma_f16(s_[j][1], afr[0], afr[1], afr[2], afr[3], kr[1], kr[3]);
        }
    }
#pragma unroll
    for (int j = 0; j < 7; j++)
#pragma unroll
        for (int hf = 0; hf < 2; hf++) {
            int col = (nh_*7 + j)*16 + hf*8 + tig*2;
            int r0 = mt*16 + gid;
            S32[r0*212 + col]       = s_[j][hf][0] * 0.125f;
            S32[r0*212 + col + 1]   = s_[j][hf][1] * 0.125f;
            S32[(r0+8)*212 + col]     = s_[j][hf][2] * 0.125f;
            S32[(r0+8)*212 + col + 1] = s_[j][hf][3] * 0.125f;
        }
    __syncthreads();

    for (int rr = 0; rr < 8; rr++) {
        int row = warp*8 + rr;
        float m = -1e30f;
        for (int j = lane; j < SEQ; j += 32) m = fmaxf(m, S32[row*212 + j]);
#pragma unroll
        for (int o = 16; o; o >>= 1) m = fmaxf(m, __shfl_xor_sync(0xffffffffu, m, o));
        float ssum = 0.f;
        for (int j = lane; j < SEQ; j += 32) {
            float e = expf(S32[row*212 + j] - m);
            S32[row*212 + j] = e;
            ssum += e;
        }
#pragma unroll
        for (int o = 16; o; o >>= 1) ssum += __shfl_xor_sync(0xffffffffu, ssum, o);
        float inv = 1.0f / ssum;
        for (int j = lane; j < 224; j += 32)
            P[row*AT_PSTR + j] = (j < SEQ) ? __float2half(S32[row*212 + j] * inv)
                                           : __ushort_as_half((unsigned short)0);
    }
    __syncthreads();

    float o_[2][2][4];
#pragma unroll
    for (int g2 = 0; g2 < 2; g2++)
#pragma unroll
        for (int m2 = 0; m2 < 2; m2++)
#pragma unroll
            for (int r = 0; r < 4; r++) o_[g2][m2][r] = 0.f;

#pragma unroll
    for (int k16 = 0; k16 < 14; k16++) {
        uint32_t pfr[4];
        ldsm4(pfr, sb + AT_P_OFF + (mt*16 + (lane & 15))*(AT_PSTR*2) + (lane >> 4)*16 + k16*32);
#pragma unroll
        for (int g2 = 0; g2 < 2; g2++) {
            uint32_t vr[4];
            ldsm4t(vr, sb + AT_V_OFF + (k16*16 + (lane & 15))*144 + (lane >> 4)*16 + (nh_*32 + g2*16)*2);
            mma_f16(o_[g2][0], pfr[0], pfr[1], pfr[2], pfr[3], vr[0], vr[1]);
            mma_f16(o_[g2][1], pfr[0], pfr[1], pfr[2], pfr[3], vr[2], vr[3]);
        }
    }
#pragma unroll
    for (int g2 = 0; g2 < 2; g2++)
#pragma unroll
        for (int m2 = 0; m2 < 2; m2++) {
            int col = h*DH + nh_*32 + g2*16 + m2*8 + tig*2;
            int r_lo = q0 + mt*16 + gid;
            int r_hi = r_lo + 8;
            if (r_lo < SEQ) {
                size_t off = (size_t)(b*SEQ + r_lo)*HID + col;
                outp[off]     += o_[g2][m2][0];
                outp[off + 1] += o_[g2][m2][1];
            }
            if (r_hi < SEQ) {
                size_t off = (size_t)(b*SEQ + r_hi)*HID + col;
                outp[off]     += o_[g2][m2][2];
                outp[off + 1] += o_[g2][m2][3];
            }
        }
}

// ---------------- pos-emb + cls assembly ----------------
__global__ void add_pos_cls_kernel(const float* __restrict__ tok,
                                   const float* __restrict__ cls,
                                   float* __restrict__ outp) {
    int idx = blockIdx.x * 256 + threadIdx.x;
    if (idx >= BS * HID) return;
    int d = idx % HID;
    int r = idx / HID;
    int b = r / SEQ, s = r % SEQ;
    float jf = (float)((d >> 1) << 1);
    float denom = powf(10000.0f, jf * (1.0f/768.0f));
    float ang = (float)s / denom;
    float pos = (d & 1) ? cosf(ang) : sinf(ang);
    float base = (s == 0) ? cls[d] : tok[(size_t)(b*NPATCH + s - 1)*HID + d];
    outp[idx] = base + pos;
}

// ---------------- LayerNorm -> half output ----------------
__global__ void __launch_bounds__(256) ln_kernel(const float* __restrict__ in,
        const float* __restrict__ gam, const float* __restrict__ bet,
        __half* __restrict__ outp) {
    __shared__ float red[16];
    int row = blockIdx.x;
    int tid = threadIdx.x;
    const float* x = in + (size_t)row * HID;
    float v0 = x[tid], v1 = x[tid+256], v2 = x[tid+512];
    float s  = v0 + v1 + v2;
    float ss = v0*v0 + v1*v1 + v2*v2;
#pragma unroll
    for (int o = 16; o; o >>= 1) {
        s  += __shfl_xor_sync(0xffffffffu, s, o);
        ss += __shfl_xor_sync(0xffffffffu, ss, o);
    }
    if ((tid & 31) == 0) { red[tid>>5] = s; red[8 + (tid>>5)] = ss; }
    __syncthreads();
    if (tid < 32) {
        float a  = (tid < 8) ? red[tid]   : 0.f;
        float bb = (tid < 8) ? red[8+tid] : 0.f;
#pragma unroll
        for (int o = 4; o; o >>= 1) {
            a  += __shfl_xor_sync(0xffffffffu, a, o);
            bb += __shfl_xor_sync(0xffffffffu, bb, o);
        }
        if (tid == 0) { red[0] = a; red[1] = bb; }
    }
    __syncthreads();
    float mean = red[0] * (1.0f/768.0f);
    float var  = red[1] * (1.0f/768.0f) - mean*mean;
    float rstd = rsqrtf(var + 1e-5f);
    __half* o = outp + (size_t)row * HID;
    o[tid]     = __float2half((v0 - mean)*rstd*gam[tid]     + bet[tid]);
    o[tid+256] = __float2half((v1 - mean)*rstd*gam[tid+256] + bet[tid+256]);
    o[tid+512] = __float2half((v2 - mean)*rstd*gam[tid+512] + bet[tid+512]);
}

// ---------------- head ----------------
__global__ void __launch_bounds__(256) head_kernel(const float* __restrict__ xin,
        const float* __restrict__ Wo, const float* __restrict__ bo,
        float* __restrict__ res) {
    __shared__ float xs[HID];
    __shared__ float logits[OUTD];
    __shared__ float red[8];
    int b = blockIdx.x;
    int tid = threadIdx.x;
    const float* src = xin + (size_t)b*SEQ*HID;
    xs[tid] = src[tid]; xs[tid+256] = src[tid+256]; xs[tid+512] = src[tid+512];
    __syncthreads();
    for (int c = tid; c < OUTD; c += 256) {
        float acc = bo[c];
#pragma unroll 8
        for (int k2 = 0; k2 < HID; k2++) acc += xs[k2] * Wo[(size_t)k2*OUTD + c];
        logits[c] = acc;
    }
    __syncthreads();
    float m = -1e30f;
    for (int c = tid; c < OUTD; c += 256) m = fmaxf(m, logits[c]);
#pragma unroll
    for (int o = 16; o; o >>= 1) m = fmaxf(m, __shfl_xor_sync(0xffffffffu, m, o));
    if ((tid & 31) == 0) red[tid>>5] = m;
    __syncthreads();
    if (tid < 32) {
        float a = (tid < 8) ? red[tid] : -1e30f;
#pragma unroll
        for (int o = 4; o; o >>= 1) a = fmaxf(a, __shfl_xor_sync(0xffffffffu, a, o));
        if (tid == 0) red[0] = a;
    }
    __syncthreads();
    m = red[0];
    __syncthreads();
    float s = 0.f;
    for (int c = tid; c < OUTD; c += 256) { float e = expf(logits[c] - m); logits[c] = e; s += e; }
#pragma unroll
    for (int o = 16; o; o >>= 1) s += __shfl_xor_sync(0xffffffffu, s, o);
    if ((tid & 31) == 0) red[tid>>5] = s;
    __syncthreads();
    if (tid < 32) {
        float a = (tid < 8) ? red[tid] : 0.f;
#pragma unroll
        for (int o = 4; o; o >>= 1) a += __shfl_xor_sync(0xffffffffu, a, o);
        if (tid == 0) red[0] = a;
    }
    __syncthreads();
    float inv = 1.0f / red[0];
    for (int c = tid; c < OUTD; c += 256) res[(size_t)b*OUTD + c] = logits[c]*inv;
}

// ---------------- launch ----------------
extern "C" void kernel_launch(void* const* d_in, const int* in_sizes, int n_in,
                              void* d_out, int out_size) {
    const float* images = (const float*)d_in[0];
    const float* Wp     = (const float*)d_in[1];
    const float* bp     = (const float*)d_in[2];
    const float* cls    = (const float*)d_in[3];
    const float* ln1_g  = (const float*)d_in[4];
    const float* ln1_b  = (const float*)d_in[5];
    const float* Wq     = (const float*)d_in[6];
    const float* bq     = (const float*)d_in[7];
    const float* Wk     = (const float*)d_in[8];
    const float* bk     = (const float*)d_in[9];
    const float* Wv     = (const float*)d_in[10];
    const float* bv     = (const float*)d_in[11];
    const float* ln2_g  = (const float*)d_in[12];
    const float* ln2_b  = (const float*)d_in[13];
    const float* W1     = (const float*)d_in[14];
    const float* b1     = (const float*)d_in[15];
    const float* W2     = (const float*)d_in[16];
    const float* b2     = (const float*)d_in[17];
    const float* Wo     = (const float*)d_in[18];
    const float* bo     = (const float*)d_in[19];
    float* outp = (float*)d_out;

    float *p_out, *p_q;
    __half *p_xh, *p_ffh, *p_wh, *p_qh, *p_kh, *p_vh;
    cudaGetSymbolAddress((void**)&p_out, g_out);
    cudaGetSymbolAddress((void**)&p_xh,  g_xh);
    cudaGetSymbolAddress((void**)&p_ffh, g_ffh);
    cudaGetSymbolAddress((void**)&p_q,   g_q);
    cudaGetSymbolAddress((void**)&p_qh,  g_qh);
    cudaGetSymbolAddress((void**)&p_kh,  g_kh);
    cudaGetSymbolAddress((void**)&p_vh,  g_vh);
    cudaGetSymbolAddress((void**)&p_wh,  g_wh);

    const __half* hWp = p_wh;
    const __half* hW1 = p_wh + WPN;
    const __half* hW2 = p_wh + WPN + W1N;
    const __half* hWq = p_wh + WPN + W1N + W2N;
    const __half* hWk = hWq + WQN;
    const __half* hWv = hWk + WQN;

    static bool attr_set = false;
    if (!attr_set) {
        cudaFuncSetAttribute(gemm_f16<0,0,0>, cudaFuncAttributeMaxDynamicSharedMemorySize, GEMM_SMEM_BYTES);
        cudaFuncSetAttribute(gemm_f16<1,0,1>, cudaFuncAttributeMaxDynamicSharedMemorySize, GEMM_SMEM_BYTES);
        cudaFuncSetAttribute(gemm_f16<0,1,0>, cudaFuncAttributeMaxDynamicSharedMemorySize, GEMM_SMEM_BYTES);
        cudaFuncSetAttribute(attn_fused_kernel, cudaFuncAttributeMaxDynamicSharedMemorySize, AT_SMEM);
        attr_set = true;
    }

    // 0) convert weights to half
    convert_weights_kernel<<<(WTOT + 255)/256, 256>>>(Wp, W1, W2, Wq, Wk, Wv, p_wh);

    // 1) patchify + patch embedding
    patchify_kernel<<<(BP*HID + 255)/256, 256>>>(images, p_xh);
    gemm_f16<0,0,0><<<dim3(HID/128, (BP+127)/128), 256, GEMM_SMEM_BYTES>>>(p_xh, hWp, bp, p_q, BP, HID, HID);
    add_pos_cls_kernel<<<(BS*HID + 255)/256, 256>>>(p_q, cls, p_out);

    // 2) transformer layers
    for (int l = 0; l < NL; l++) {
        ln_kernel<<<BS, 256>>>(p_out, ln1_g + l*HID, ln1_b + l*HID, p_xh);
        qkv_mma_kernel<<<dim3((BS+127)/128, NH, 3), 256>>>(p_xh,
            hWq + (size_t)l*NH*DH*DH, bq + l*NH*DH, p_qh,
            hWk + (size_t)l*NH*DH*DH, bk + l*NH*DH, p_kh,
            hWv + (size_t)l*NH*DH*DH, bv + l*NH*DH, p_vh);
        attn_fused_kernel<<<dim3(4, BATCH*NH), 256, AT_SMEM>>>(p_qh, p_kh, p_vh, p_out);
        ln_kernel<<<BS, 256>>>(p_out, ln2_g + l*HID, ln2_b + l*HID, p_xh);
        gemm_f16<1,0,1><<<dim3(DFF/128, (BS+127)/128), 256, GEMM_SMEM_BYTES>>>(p_xh, hW1 + (size_t)l*HID*DFF, b1 + l*DFF, p_ffh, BS, DFF, HID);
        gemm_f16<0,1,0><<<dim3(HID/128, (BS+127)/128), 256, GEMM_SMEM_BYTES>>>(p_ffh, hW2 + (size_t)l*DFF*HID, b2 + l*HID, p_out, BS, HID, DFF);
    }

    // 3) classification head + softmax
    head_kernel<<<BATCH, 256>>>(p_out, Wo, bo, outp);
}

// round 16
// speedup vs baseline: 1.7190x; 1.0570x over previous
#include <cuda_runtime.h>
#include <cuda_fp16.h>
#include <math.h>
#include <stdint.h>

#define BATCH 64
#define SEQ 197
#define NPATCH 196
#define HID 768
#define NH 12
#define DH 64
#define DFF 3072
#define NL 4
#define OUTD 1000

#define BS (BATCH*SEQ)      // 12608
#define BP (BATCH*NPATCH)   // 12544

#define WPN (768*768)
#define W1N (NL*HID*DFF)
#define W2N (NL*DFF*HID)
#define WQN (NL*NH*DH*DH)
#define WTOT (WPN + W1N + W2N + 3*WQN)

// ---------------- scratch (static device globals; no allocations) ----------------
__device__ float  g_out[(size_t)BS*HID];
__device__ __half g_xh [(size_t)BS*HID];     // half activations (ln out / patches)
__device__ __half g_ffh[(size_t)BS*DFF];     // half FF1 output
__device__ __half g_qh [(size_t)BS*HID];
__device__ __half g_kh [(size_t)BS*HID];
__device__ __half g_vh [(size_t)BS*HID];
__device__ __half g_wh [(size_t)WTOT];       // half weights {Wp, W1, W2, Wq, Wk, Wv}

// ---------------- weight convert ----------------
__global__ void convert_weights_kernel(const float* __restrict__ Wp,
                                       const float* __restrict__ W1,
                                       const float* __restrict__ W2,
                                       const float* __restrict__ Wq,
                                       const float* __restrict__ Wk,
                                       const float* __restrict__ Wv,
                                       __half* __restrict__ dst) {
    size_t idx = (size_t)blockIdx.x * 256 + threadIdx.x;
    if (idx >= (size_t)WTOT) return;
    float v;
    if (idx < WPN)                       v = Wp[idx];
    else if (idx < (size_t)WPN + W1N)    v = W1[idx - WPN];
    else if (idx < (size_t)WPN + W1N + W2N) v = W2[idx - WPN - W1N];
    else {
        size_t rel = idx - WPN - W1N - W2N;
        size_t z = rel / WQN, r = rel % WQN;
        v = (z == 0) ? Wq[r] : (z == 1) ? Wk[r] : Wv[r];
    }
    dst[idx] = __float2half(v);
}

// ---------------- patchify -> half patches ----------------
__global__ void patchify_kernel(const float* __restrict__ img, __half* __restrict__ patches) {
    int idx = blockIdx.x * 256 + threadIdx.x;
    if (idx >= BP * HID) return;
    int k = idx % HID;
    int m = idx / HID;
    int b = m / NPATCH, p = m % NPATCH;
    int pr = p / 14, pc = p % 14;
    int c = k >> 8;
    int ij = k & 255;
    int i = ij >> 4, j = ij & 15;
    patches[idx] = __float2half(img[(((b*3 + c)*224) + pr*16 + i)*224 + pc*16 + j]);
}

// ---------------- cls row init: out[b,0,:] = cls + pos(0,:) ----------------
__global__ void cls_row_kernel(const float* __restrict__ cls, float* __restrict__ outp) {
    int idx = blockIdx.x * 256 + threadIdx.x;
    if (idx >= BATCH * HID) return;
    int d = idx % HID, b = idx / HID;
    // s = 0: sin(0)=0 (even d), cos(0)=1 (odd d)
    outp[(size_t)b*SEQ*HID + d] = cls[d] + ((d & 1) ? 1.0f : 0.0f);
}

__device__ __forceinline__ float gelu_exact(float x) {
    return 0.5f * x * (1.0f + erff(x * 0.7071067811865476f));
}

__device__ __forceinline__ float pos_emb(int s, int d) {
    float jf = (float)((d >> 1) << 1);
    float denom = powf(10000.0f, jf * (1.0f/768.0f));
    float ang = (float)s / denom;
    return (d & 1) ? cosf(ang) : sinf(ang);
}

__device__ __forceinline__ void mma_f16(float c[4], uint32_t a0, uint32_t a1,
        uint32_t a2, uint32_t a3, uint32_t b0, uint32_t b1) {
    asm volatile(
        "mma.sync.aligned.m16n8k16.row.col.f32.f16.f16.f32 "
        "{%0,%1,%2,%3}, {%4,%5,%6,%7}, {%8,%9}, {%0,%1,%2,%3};"
        : "+f"(c[0]), "+f"(c[1]), "+f"(c[2]), "+f"(c[3])
        : "r"(a0), "r"(a1), "r"(a2), "r"(a3), "r"(b0), "r"(b1));
}

__device__ __forceinline__ void ldsm4(uint32_t r[4], uint32_t addr) {
    asm volatile("ldmatrix.sync.aligned.m8n8.x4.shared.b16 {%0,%1,%2,%3}, [%4];"
        : "=r"(r[0]), "=r"(r[1]), "=r"(r[2]), "=r"(r[3]) : "r"(addr));
}
__device__ __forceinline__ void ldsm4t(uint32_t r[4], uint32_t addr) {
    asm volatile("ldmatrix.sync.aligned.m8n8.x4.trans.shared.b16 {%0,%1,%2,%3}, [%4];"
        : "=r"(r[0]), "=r"(r[1]), "=r"(r[2]), "=r"(r[3]) : "r"(addr));
}

__device__ __forceinline__ void cp16(void* dst, const void* src) {
    uint32_t d = (uint32_t)__cvta_generic_to_shared(dst);
    asm volatile("cp.async.cg.shared.global [%0], [%1], 16;" :: "r"(d), "l"(src));
}
__device__ __forceinline__ void cp16s(uint32_t dst_shared, const void* src) {
    asm volatile("cp.async.cg.shared.global [%0], [%1], 16;" :: "r"(dst_shared), "l"(src));
}
__device__ __forceinline__ void cp_commit() { asm volatile("cp.async.commit_group;"); }
__device__ __forceinline__ void cp_wait2()  { asm volatile("cp.async.wait_group 2;"); }
__device__ __forceinline__ void cp_wait0()  { asm volatile("cp.async.wait_group 0;"); }

// ---------------- FP16 tensor-core GEMM (128x128, 256 thr, 4-stage) ----------
#define ASTR 40
#define BSTR 264
#define A_STAGE_H (128*ASTR)
#define B_STAGE_H (32*BSTR)
#define A_STAGE_B (A_STAGE_H*2)
#define B_STAGE_B (B_STAGE_H*2)
#define NSTAGE 4
#define GEMM_SMEM_BYTES (NSTAGE*(A_STAGE_B + B_STAGE_B))   // 108544

// POS mode: C rows are patch indices; write fp32 to out[b*197+(p+1)] with pos-emb added.
template<int ACT, int RESID, int OUTH, int POS>
__global__ void __launch_bounds__(256) gemm_f16(
        const __half* __restrict__ A, const __half* __restrict__ B,
        const float* __restrict__ bias, void* __restrict__ Cv,
        int M, int N, int K)
{
    extern __shared__ uint32_t smem_dyn[];
    __half* Ash = (__half*)smem_dyn;
    __half* Bsh = (__half*)smem_dyn + NSTAGE*A_STAGE_H;
    uint32_t s_base = (uint32_t)__cvta_generic_to_shared(smem_dyn);
    uint32_t a_s32 = s_base;
    uint32_t b_s32 = s_base + NSTAGE*A_STAGE_B;

    int tid  = threadIdx.x;
    int lane = tid & 31;
    int warp = tid >> 5;
    int warp_m = (warp >> 2) * 64;
    int warp_n = (warp & 3) * 32;
    int gid = lane >> 2, tig = lane & 3;

    int row0 = blockIdx.y * 128, col0 = blockIdx.x * 128;

    int rowA = tid >> 1;
    int akh  = (tid & 1) * 16;
    int arow = row0 + rowA; if (arow >= M) arow = M - 1;
    const __half* Aptr = A + (size_t)arow * K + akh;
    int rowB = tid >> 3;
    int nch  = (tid & 7) * 16;
    const __half* Bptr = B + (size_t)rowB * N + col0 + nch;

    uint32_t aoff = (uint32_t)((lane & 15) * (ASTR*2) + (lane >> 4) * 16);
    uint32_t boff = (uint32_t)((lane & 15) * (BSTR*2) + (lane >> 4) * 16);

    float acc[4][4][4];
#pragma unroll
    for (int i = 0; i < 4; i++)
#pragma unroll
        for (int j = 0; j < 4; j++)
#pragma unroll
            for (int r = 0; r < 4; r++) acc[i][j][r] = 0.f;

    int nt = K >> 5;

#pragma unroll
    for (int s = 0; s < NSTAGE - 1; s++) {
        const __half* ap = Aptr + (size_t)s * 32;
        cp16(Ash + (size_t)s*A_STAGE_H + rowA*ASTR + akh,     ap);
        cp16(Ash + (size_t)s*A_STAGE_H + rowA*ASTR + akh + 8, ap + 8);
        const __half* bp = Bptr + (size_t)s * 32 * N;
        cp16(Bsh + (size_t)s*B_STAGE_H + rowB*BSTR + nch,     bp);
        cp16(Bsh + (size_t)s*B_STAGE_H + rowB*BSTR + nch + 8, bp + 8);
        cp_commit();
    }

    for (int t = 0; t < nt; t++) {
        cp_wait2();
        __syncthreads();
        int buf = t % NSTAGE;
        uint32_t abase = a_s32 + buf*A_STAGE_B + warp_m*(ASTR*2) + aoff;
        uint32_t bbase = b_s32 + buf*B_STAGE_B + warp_n*2 + boff;
#pragma unroll
        for (int k16 = 0; k16 < 2; k16++) {
            uint32_t ak = abase + k16*32;
            uint32_t bk = bbase + k16*16*(BSTR*2);
            uint32_t afr[4][4];
#pragma unroll
            for (int ma = 0; ma < 4; ma++)
                ldsm4(afr[ma], ak + ma*16*(ASTR*2));
            uint32_t bq[2][4];
#pragma unroll
            for (int nb = 0; nb < 2; nb++)
                ldsm4t(bq[nb], bk + nb*32);
#pragma unroll
            for (int ma = 0; ma < 4; ma++) {
#pragma unroll
                for (int nb = 0; nb < 2; nb++) {
                    mma_f16(acc[ma][nb*2],   afr[ma][0], afr[ma][1], afr[ma][2], afr[ma][3],
                            bq[nb][0], bq[nb][1]);
                    mma_f16(acc[ma][nb*2+1], afr[ma][0], afr[ma][1], afr[ma][2], afr[ma][3],
                            bq[nb][2], bq[nb][3]);
                }
            }
        }
        if (t + NSTAGE - 1 < nt) {
            int s = (t + NSTAGE - 1) % NSTAGE;
            const __half* ap = Aptr + (size_t)(t + NSTAGE - 1) * 32;
            cp16(Ash + (size_t)s*A_STAGE_H + rowA*ASTR + akh,     ap);
            cp16(Ash + (size_t)s*A_STAGE_H + rowA*ASTR + akh + 8, ap + 8);
            const __half* bp = Bptr + (size_t)(t + NSTAGE - 1) * 32 * N;
            cp16(Bsh + (size_t)s*B_STAGE_H + rowB*BSTR + nch,     bp);
            cp16(Bsh + (size_t)s*B_STAGE_H + rowB*BSTR + nch + 8, bp + 8);
        }
        cp_commit();
    }

#pragma unroll
    for (int ma = 0; ma < 4; ma++) {
        int r_lo = row0 + warp_m + ma * 16 + gid;
        int r_hi = r_lo + 8;
#pragma unroll
        for (int na = 0; na < 4; na++) {
            int c = col0 + warp_n + na * 8 + tig * 2;
            float bc0 = bias[c], bc1 = bias[c + 1];
            if (r_lo < M) {
                float v0 = acc[ma][na][0] + bc0;
                float v1 = acc[ma][na][1] + bc1;
                if (ACT == 1) { v0 = gelu_exact(v0); v1 = gelu_exact(v1); }
                if (POS) {
                    int bb = r_lo / NPATCH, s = r_lo % NPATCH + 1;
                    size_t off = (size_t)(bb*SEQ + s) * N + c;
                    ((float*)Cv)[off]     = v0 + pos_emb(s, c);
                    ((float*)Cv)[off + 1] = v1 + pos_emb(s, c + 1);
                } else {
                    size_t off = (size_t)r_lo * N + c;
                    if (OUTH) {
                        *(__half2*)((__half*)Cv + off) = __floats2half2_rn(v0, v1);
                    } else if (RESID) {
                        ((float*)Cv)[off] += v0; ((float*)Cv)[off + 1] += v1;
                    } else {
                        ((float*)Cv)[off]  = v0; ((float*)Cv)[off + 1]  = v1;
                    }
                }
            }
            if (r_hi < M) {
                float v2 = acc[ma][na][2] + bc0;
                float v3 = acc[ma][na][3] + bc1;
                if (ACT == 1) { v2 = gelu_exact(v2); v3 = gelu_exact(v3); }
                if (POS) {
                    int bb = r_hi / NPATCH, s = r_hi % NPATCH + 1;
                    size_t off = (size_t)(bb*SEQ + s) * N + c;
                    ((float*)Cv)[off]     = v2 + pos_emb(s, c);
                    ((float*)Cv)[off + 1] = v3 + pos_emb(s, c + 1);
                } else {
                    size_t off = (size_t)r_hi * N + c;
                    if (OUTH) {
                        *(__half2*)((__half*)Cv + off) = __floats2half2_rn(v2, v3);
                    } else if (RESID) {
                        ((float*)Cv)[off] += v2; ((float*)Cv)[off + 1] += v3;
                    } else {
                        ((float*)Cv)[off]  = v2; ((float*)Cv)[off + 1]  = v3;
                    }
                }
            }
        }
    }
}

// ---------------- QKV via tensor cores: per-head 128x64x64 mma ----------------
__global__ void __launch_bounds__(256) qkv_mma_kernel(const __half* __restrict__ x,
        const __half* __restrict__ Wq, const float* __restrict__ bq, __half* __restrict__ oq,
        const __half* __restrict__ Wk, const float* __restrict__ bk, __half* __restrict__ ok,
        const __half* __restrict__ Wv, const float* __restrict__ bv, __half* __restrict__ ov) {
    const __half* W; const float* bias; __half* outp;
    if (blockIdx.z == 0)      { W = Wq; bias = bq; outp = oq; }
    else if (blockIdx.z == 1) { W = Wk; bias = bk; outp = ok; }
    else                      { W = Wv; bias = bv; outp = ov; }

    __shared__ __align__(16) __half Xs[128][72];
    __shared__ __align__(16) __half Ws[64][72];
    uint32_t xs32 = (uint32_t)__cvta_generic_to_shared(Xs);
    uint32_t ws32 = (uint32_t)__cvta_generic_to_shared(Ws);

    int tid = threadIdx.x;
    int lane = tid & 31, warp = tid >> 5;
    int gid = lane >> 2, tig = lane & 3;
    int h = blockIdx.y;
    int row0 = blockIdx.x * 128;

#pragma unroll
    for (int i = 0; i < 4; i++) {
        int op = tid + i * 256;
        int row = op >> 3, c = op & 7;
        int grow = row0 + row; if (grow >= BS) grow = BS - 1;
        cp16s(xs32 + row*144 + c*16, x + (size_t)grow*HID + h*DH + c*8);
    }
#pragma unroll
    for (int i = 0; i < 2; i++) {
        int op = tid + i * 256;
        int row = op >> 3, c = op & 7;
        cp16s(ws32 + row*144 + c*16, W + (size_t)h*DH*DH + row*DH + c*8);
    }
    cp_commit();
    cp_wait0();
    __syncthreads();

    float acc[4][2][4];
#pragma unroll
    for (int g = 0; g < 4; g++)
#pragma unroll
        for (int hf = 0; hf < 2; hf++)
#pragma unroll
            for (int r = 0; r < 4; r++) acc[g][hf][r] = 0.f;

#pragma unroll
    for (int k16 = 0; k16 < 4; k16++) {
        uint32_t afr[4];
        ldsm4(afr, xs32 + (warp*16 + (lane & 15))*144 + (lane >> 4)*16 + k16*32);
#pragma unroll
        for (int g = 0; g < 4; g++) {
            uint32_t kr[4];
            ldsm4(kr, ws32 + (g*16 + (lane & 15))*144 + (lane >> 4)*16 + k16*32);
            mma_f16(acc[g][0], afr[0], afr[1], afr[2], afr[3], kr[0], kr[2]);
            mma_f16(acc[g][1], afr[0], afr[1], afr[2], afr[3], kr[1], kr[3]);
        }
    }

    int r_lo = row0 + warp*16 + gid;
    int r_hi = r_lo + 8;
#pragma unroll
    for (int g = 0; g < 4; g++)
#pragma unroll
        for (int hf = 0; hf < 2; hf++) {
            int e = g*16 + hf*8 + tig*2;
            float bc0 = bias[h*DH + e], bc1 = bias[h*DH + e + 1];
            if (r_lo < BS)
                *(__half2*)(outp + (size_t)r_lo*HID + h*DH + e) =
                    __floats2half2_rn(acc[g][hf][0] + bc0, acc[g][hf][1] + bc1);
            if (r_hi < BS)
                *(__half2*)(outp + (size_t)r_hi*HID + h*DH + e) =
                    __floats2half2_rn(acc[g][hf][2] + bc0, acc[g][hf][3] + bc1);
        }
}

// ---------------- fused attention: S=QK^T, softmax, O += P V ----------------
#define AT_Q_OFF 0
#define AT_K_OFF 9216
#define AT_V_OFF 41472
#define AT_S_OFF 73728
#define AT_P_OFF 128000
#define AT_PSTR  232
#define AT_SMEM  (AT_P_OFF + 64*AT_PSTR*2)   // 157696

__global__ void __launch_bounds__(256) attn_fused_kernel(
        const __half* __restrict__ qh, const __half* __restrict__ kh,
        const __half* __restrict__ vh, float* __restrict__ outp)
{
    extern __shared__ char smem[];
    uint32_t sb = (uint32_t)__cvta_generic_to_shared(smem);
    float* S32 = (float*)(smem + AT_S_OFF);
    __half* P  = (__half*)(smem + AT_P_OFF);

    int tid = threadIdx.x;
    int lane = tid & 31, warp = tid >> 5;
    int gid = lane >> 2, tig = lane & 3;
    int bh = blockIdx.y;
    int b = bh / NH, h = bh % NH;
    int q0 = blockIdx.x * 64;

#pragma unroll
    for (int i = 0; i < 2; i++) {
        int op = tid + i * 256;
        int row = op >> 3, c = op & 7;
        int grow = q0 + row; if (grow > SEQ - 1) grow = SEQ - 1;
        cp16s(sb + AT_Q_OFF + row*144 + c*16, qh + (size_t)(b*SEQ + grow)*HID + h*DH + c*8);
    }
#pragma unroll
    for (int i = 0; i < 7; i++) {
        int op = tid + i * 256;
        int row = op >> 3, c = op & 7;
        int grow = row > SEQ - 1 ? SEQ - 1 : row;
        const size_t goff = (size_t)(b*SEQ + grow)*HID + h*DH + c*8;
        cp16s(sb + AT_K_OFF + row*144 + c*16, kh + goff);
        cp16s(sb + AT_V_OFF + row*144 + c*16, vh + goff);
    }
    cp_commit();
    cp_wait0();
    __syncthreads();

    int mt = warp >> 1;
    int nh_ = warp & 1;

    float s_[7][2][4];
#pragma unroll
    for (int j = 0; j < 7; j++)
#pragma unroll
        for (int hf = 0; hf < 2; hf++)
#pragma unroll
            for (int r = 0; r < 4; r++) s_[j][hf][r] = 0.f;

#pragma unroll
    for (int k16 = 0; k16 < 4; k16++) {
        uint32_t afr[4];
        ldsm4(afr, sb + AT_Q_OFF + (mt*16 + (lane & 15))*144 + (lane >> 4)*16 + k16*32);
#pragma unroll
        for (int j = 0; j < 7; j++) {
            int g = nh_ * 7 + j;
            uint32_t kr[4];
            ldsm4(kr, sb + AT_K_OFF + (g*16 + (lane & 15))*144 + (lane >> 4)*16 + k16*32);
            mma_f16(s_[j][0], afr[0], afr[1], afr[2], afr[3], kr[0], kr[2]);
            mma_f16(s_[j][1], afr[0], afr[1], afr[2], afr[3], kr[1], kr[3]);
        }
    }
#pragma unroll
    for (int j = 0; j < 7; j++)
#pragma unroll
        for (int hf = 0; hf < 2; hf++) {
            int col = (nh_*7 + j)*16 + hf*8 + tig*2;
            int r0 = mt*16 + gid;
            S32[r0*212 + col]       = s_[j][hf][0] * 0.125f;
            S32[r0*212 + col + 1]   = s_[j][hf][1] * 0.125f;
            S32[(r0+8)*212 + col]     = s_[j][hf][2] * 0.125f;
            S32[(r0+8)*212 + col + 1] = s_[j][hf][3] * 0.125f;
        }
    __syncthreads();

    for (int rr = 0; rr < 8; rr++) {
        int row = warp*8 + rr;
        float m = -1e30f;
        for (int j = lane; j < SEQ; j += 32) m = fmaxf(m, S32[row*212 + j]);
#pragma unroll
        for (int o = 16; o; o >>= 1) m = fmaxf(m, __shfl_xor_sync(0xffffffffu, m, o));
        float ssum = 0.f;
        for (int j = lane; j < SEQ; j += 32) {
            float e = expf(S32[row*212 + j] - m);
            S32[row*212 + j] = e;
            ssum += e;
        }
#pragma unroll
        for (int o = 16; o; o >>= 1) ssum += __shfl_xor_sync(0xffffffffu, ssum, o);
        float inv = 1.0f / ssum;
        for (int j = lane; j < 224; j += 32)
            P[row*AT_PSTR + j] = (j < SEQ) ? __float2half(S32[row*212 + j] * inv)
                                           : __ushort_as_half((unsigned short)0);
    }
    __syncthreads();

    float o_[2][2][4];
#pragma unroll
    for (int g2 = 0; g2 < 2; g2++)
#pragma unroll
        for (int m2 = 0; m2 < 2; m2++)
#pragma unroll
            for (int r = 0; r < 4; r++) o_[g2][m2][r] = 0.f;

#pragma unroll
    for (int k16 = 0; k16 < 14; k16++) {
        uint32_t pfr[4];
        ldsm4(pfr, sb + AT_P_OFF + (mt*16 + (lane & 15))*(AT_PSTR*2) + (lane >> 4)*16 + k16*32);
#pragma unroll
        for (int g2 = 0; g2 < 2; g2++) {
            uint32_t vr[4];
            ldsm4t(vr, sb + AT_V_OFF + (k16*16 + (lane & 15))*144 + (lane >> 4)*16 + (nh_*32 + g2*16)*2);
            mma_f16(o_[g2][0], pfr[0], pfr[1], pfr[2], pfr[3], vr[0], vr[1]);
            mma_f16(o_[g2][1], pfr[0], pfr[1], pfr[2], pfr[3], vr[2], vr[3]);
        }
    }
#pragma unroll
    for (int g2 = 0; g2 < 2; g2++)
#pragma unroll
        for (int m2 = 0; m2 < 2; m2++) {
            int col = h*DH + nh_*32 + g2*16 + m2*8 + tig*2;
            int r_lo = q0 + mt*16 + gid;
            int r_hi = r_lo + 8;
            if (r_lo < SEQ) {
                size_t off = (size_t)(b*SEQ + r_lo)*HID + col;
                outp[off]     += o_[g2][m2][0];
                outp[off + 1] += o_[g2][m2][1];
            }
            if (r_hi < SEQ) {
                size_t off = (size_t)(b*SEQ + r_hi)*HID + col;
                outp[off]     += o_[g2][m2][2];
                outp[off + 1] += o_[g2][m2][3];
            }
        }
}

// ---------------- LayerNorm -> half output ----------------
__global__ void __launch_bounds__(256) ln_kernel(const float* __restrict__ in,
        const float* __restrict__ gam, const float* __restrict__ bet,
        __half* __restrict__ outp) {
    __shared__ float red[16];
    int row = blockIdx.x;
    int tid = threadIdx.x;
    const float* x = in + (size_t)row * HID;
    float v0 = x[tid], v1 = x[tid+256], v2 = x[tid+512];
    float s  = v0 + v1 + v2;
    float ss = v0*v0 + v1*v1 + v2*v2;
#pragma unroll
    for (int o = 16; o; o >>= 1) {
        s  += __shfl_xor_sync(0xffffffffu, s, o);
        ss += __shfl_xor_sync(0xffffffffu, ss, o);
    }
    if ((tid & 31) == 0) { red[tid>>5] = s; red[8 + (tid>>5)] = ss; }
    __syncthreads();
    if (tid < 32) {
        float a  = (tid < 8) ? red[tid]   : 0.f;
        float bb = (tid < 8) ? red[8+tid] : 0.f;
#pragma unroll
        for (int o = 4; o; o >>= 1) {
            a  += __shfl_xor_sync(0xffffffffu, a, o);
            bb += __shfl_xor_sync(0xffffffffu, bb, o);
        }
        if (tid == 0) { red[0] = a; red[1] = bb; }
    }
    __syncthreads();
    float mean = red[0] * (1.0f/768.0f);
    float var  = red[1] * (1.0f/768.0f) - mean*mean;
    float rstd = rsqrtf(var + 1e-5f);
    __half* o = outp + (size_t)row * HID;
    o[tid]     = __float2half((v0 - mean)*rstd*gam[tid]     + bet[tid]);
    o[tid+256] = __float2half((v1 - mean)*rstd*gam[tid+256] + bet[tid+256]);
    o[tid+512] = __float2half((v2 - mean)*rstd*gam[tid+512] + bet[tid+512]);
}

// ---------------- head ----------------
__global__ void __launch_bounds__(256) head_kernel(const float* __restrict__ xin,
        const float* __restrict__ Wo, const float* __restrict__ bo,
        float* __restrict__ res) {
    __shared__ float xs[HID];
    __shared__ float logits[OUTD];
    __shared__ float red[8];
    int b = blockIdx.x;
    int tid = threadIdx.x;
    const float* src = xin + (size_t)b*SEQ*HID;
    xs[tid] = src[tid]; xs[tid+256] = src[tid+256]; xs[tid+512] = src[tid+512];
    __syncthreads();
    for (int c = tid; c < OUTD; c += 256) {
        float acc = bo[c];
#pragma unroll 8
        for (int k2 = 0; k2 < HID; k2++) acc += xs[k2] * Wo[(size_t)k2*OUTD + c];
        logits[c] = acc;
    }
    __syncthreads();
    float m = -1e30f;
    for (int c = tid; c < OUTD; c += 256) m = fmaxf(m, logits[c]);
#pragma unroll
    for (int o = 16; o; o >>= 1) m = fmaxf(m, __shfl_xor_sync(0xffffffffu, m, o));
    if ((tid & 31) == 0) red[tid>>5] = m;
    __syncthreads();
    if (tid < 32) {
        float a = (tid < 8) ? red[tid] : -1e30f;
#pragma unroll
        for (int o = 4; o; o >>= 1) a = fmaxf(a, __shfl_xor_sync(0xffffffffu, a, o));
        if (tid == 0) red[0] = a;
    }
    __syncthreads();
    m = red[0];
    __syncthreads();
    float s = 0.f;
    for (int c = tid; c < OUTD; c += 256) { float e = expf(logits[c] - m); logits[c] = e; s += e; }
#pragma unroll
    for (int o = 16; o; o >>= 1) s += __shfl_xor_sync(0xffffffffu, s, o);
    if ((tid & 31) == 0) red[tid>>5] = s;
    __syncthreads();
    if (tid < 32) {
        float a = (tid < 8) ? red[tid] : 0.f;
#pragma unroll
        for (int o = 4; o; o >>= 1) a += __shfl_xor_sync(0xffffffffu, a, o);
        if (tid == 0) red[0] = a;
    }
    __syncthreads();
    float inv = 1.0f / red[0];
    for (int c = tid; c < OUTD; c += 256) res[(size_t)b*OUTD + c] = logits[c]*inv;
}

// ---------------- launch ----------------
extern "C" void kernel_launch(void* const* d_in, const int* in_sizes, int n_in,
                              void* d_out, int out_size) {
    const float* images = (const float*)d_in[0];
    const float* Wp     = (const float*)d_in[1];
    const float* bp     = (const float*)d_in[2];
    const float* cls    = (const float*)d_in[3];
    const float* ln1_g  = (const float*)d_in[4];
    const float* ln1_b  = (const float*)d_in[5];
    const float* Wq     = (const float*)d_in[6];
    const float* bq     = (const float*)d_in[7];
    const float* Wk     = (const float*)d_in[8];
    const float* bk     = (const float*)d_in[9];
    const float* Wv     = (const float*)d_in[10];
    const float* bv     = (const float*)d_in[11];
    const float* ln2_g  = (const float*)d_in[12];
    const float* ln2_b  = (const float*)d_in[13];
    const float* W1     = (const float*)d_in[14];
    const float* b1     = (const float*)d_in[15];
    const float* W2     = (const float*)d_in[16];
    const float* b2     = (const float*)d_in[17];
    const float* Wo     = (const float*)d_in[18];
    const float* bo     = (const float*)d_in[19];
    float* outp = (float*)d_out;

    float *p_out;
    __half *p_xh, *p_ffh, *p_wh, *p_qh, *p_kh, *p_vh;
    cudaGetSymbolAddress((void**)&p_out, g_out);
    cudaGetSymbolAddress((void**)&p_xh,  g_xh);
    cudaGetSymbolAddress((void**)&p_ffh, g_ffh);
    cudaGetSymbolAddress((void**)&p_qh,  g_qh);
    cudaGetSymbolAddress((void**)&p_kh,  g_kh);
    cudaGetSymbolAddress((void**)&p_vh,  g_vh);
    cudaGetSymbolAddress((void**)&p_wh,  g_wh);

    const __half* hWp = p_wh;
    const __half* hW1 = p_wh + WPN;
    const __half* hW2 = p_wh + WPN + W1N;
    const __half* hWq = p_wh + WPN + W1N + W2N;
    const __half* hWk = hWq + WQN;
    const __half* hWv = hWk + WQN;

    static bool attr_set = false;
    if (!attr_set) {
        cudaFuncSetAttribute(gemm_f16<0,0,0,1>, cudaFuncAttributeMaxDynamicSharedMemorySize, GEMM_SMEM_BYTES);
        cudaFuncSetAttribute(gemm_f16<1,0,1,0>, cudaFuncAttributeMaxDynamicSharedMemorySize, GEMM_SMEM_BYTES);
        cudaFuncSetAttribute(gemm_f16<0,1,0,0>, cudaFuncAttributeMaxDynamicSharedMemorySize, GEMM_SMEM_BYTES);
        cudaFuncSetAttribute(attn_fused_kernel, cudaFuncAttributeMaxDynamicSharedMemorySize, AT_SMEM);
        attr_set = true;
    }

    // 0) convert weights to half
    convert_weights_kernel<<<(WTOT + 255)/256, 256>>>(Wp, W1, W2, Wq, Wk, Wv, p_wh);

    // 1) patchify + patch embedding (pos-emb fused into epilogue) + cls rows
    patchify_kernel<<<(BP*HID + 255)/256, 256>>>(images, p_xh);
    gemm_f16<0,0,0,1><<<dim3(HID/128, (BP+127)/128), 256, GEMM_SMEM_BYTES>>>(p_xh, hWp, bp, p_out, BP, HID, HID);
    cls_row_kernel<<<(BATCH*HID + 255)/256, 256>>>(cls, p_out);

    // 2) transformer layers
    for (int l = 0; l < NL; l++) {
        ln_kernel<<<BS, 256>>>(p_out, ln1_g + l*HID, ln1_b + l*HID, p_xh);
        qkv_mma_kernel<<<dim3((BS+127)/128, NH, 3), 256>>>(p_xh,
            hWq + (size_t)l*NH*DH*DH, bq + l*NH*DH, p_qh,
            hWk + (size_t)l*NH*DH*DH, bk + l*NH*DH, p_kh,
            hWv + (size_t)l*NH*DH*DH, bv + l*NH*DH, p_vh);
        attn_fused_kernel<<<dim3(4, BATCH*NH), 256, AT_SMEM>>>(p_qh, p_kh, p_vh, p_out);
        ln_kernel<<<BS, 256>>>(p_out, ln2_g + l*HID, ln2_b + l*HID, p_xh);
        gemm_f16<1,0,1,0><<<dim3(DFF/128, (BS+127)/128), 256, GEMM_SMEM_BYTES>>>(p_xh, hW1 + (size_t)l*HID*DFF, b1 + l*DFF, p_ffh, BS, DFF, HID);
        gemm_f16<0,1,0,0><<<dim3(HID/128, (BS+127)/128), 256, GEMM_SMEM_BYTES>>>(p_ffh, hW2 + (size_t)l*DFF*HID, b2 + l*HID, p_out, BS, HID, DFF);
    }

    // 3) classification head + softmax
    head_kernel<<<BATCH, 256>>>(p_out, Wo, bo, outp);
}

// round 17
// speedup vs baseline: 2.2290x; 1.2967x over previous
#include <cuda_runtime.h>
#include <cuda_fp16.h>
#include <math.h>
#include <stdint.h>

#define BATCH 64
#define SEQ 197
#define NPATCH 196
#define HID 768
#define NH 12
#define DH 64
#define DFF 3072
#define NL 4
#define OUTD 1000

#define BS (BATCH*SEQ)      // 12608
#define BP (BATCH*NPATCH)   // 12544

#define WPN (768*768)
#define W1N (NL*HID*DFF)
#define W2N (NL*DFF*HID)
#define WQN (NL*NH*DH*DH)
#define WTOT (WPN + W1N + W2N + 3*WQN)

// ---------------- scratch (static device globals; no allocations) ----------------
__device__ float  g_out[(size_t)BS*HID];
__device__ __half g_xh [(size_t)BS*HID];
__device__ __half g_ffh[(size_t)BS*DFF];
__device__ __half g_qh [(size_t)BS*HID];
__device__ __half g_kh [(size_t)BS*HID];
__device__ __half g_vh [(size_t)BS*HID];
__device__ __half g_wh [(size_t)WTOT];

// ---------------- weight convert ----------------
__global__ void convert_weights_kernel(const float* __restrict__ Wp,
                                       const float* __restrict__ W1,
                                       const float* __restrict__ W2,
                                       const float* __restrict__ Wq,
                                       const float* __restrict__ Wk,
                                       const float* __restrict__ Wv,
                                       __half* __restrict__ dst) {
    size_t idx = (size_t)blockIdx.x * 256 + threadIdx.x;
    if (idx >= (size_t)WTOT) return;
    float v;
    if (idx < WPN)                       v = Wp[idx];
    else if (idx < (size_t)WPN + W1N)    v = W1[idx - WPN];
    else if (idx < (size_t)WPN + W1N + W2N) v = W2[idx - WPN - W1N];
    else {
        size_t rel = idx - WPN - W1N - W2N;
        size_t z = rel / WQN, r = rel % WQN;
        v = (z == 0) ? Wq[r] : (z == 1) ? Wk[r] : Wv[r];
    }
    dst[idx] = __float2half(v);
}

// ---------------- patchify -> half patches ----------------
__global__ void patchify_kernel(const float* __restrict__ img, __half* __restrict__ patches) {
    int idx = blockIdx.x * 256 + threadIdx.x;
    if (idx >= BP * HID) return;
    int k = idx % HID;
    int m = idx / HID;
    int b = m / NPATCH, p = m % NPATCH;
    int pr = p / 14, pc = p % 14;
    int c = k >> 8;
    int ij = k & 255;
    int i = ij >> 4, j = ij & 15;
    patches[idx] = __float2half(img[(((b*3 + c)*224) + pr*16 + i)*224 + pc*16 + j]);
}

// ---------------- cls row init ----------------
__global__ void cls_row_kernel(const float* __restrict__ cls, float* __restrict__ outp) {
    int idx = blockIdx.x * 256 + threadIdx.x;
    if (idx >= BATCH * HID) return;
    int d = idx % HID, b = idx / HID;
    outp[(size_t)b*SEQ*HID + d] = cls[d] + ((d & 1) ? 1.0f : 0.0f);
}

__device__ __forceinline__ float gelu_exact(float x) {
    return 0.5f * x * (1.0f + erff(x * 0.7071067811865476f));
}

__device__ __forceinline__ float pos_emb(int s, int d) {
    float jf = (float)((d >> 1) << 1);
    float denom = powf(10000.0f, jf * (1.0f/768.0f));
    float ang = (float)s / denom;
    return (d & 1) ? cosf(ang) : sinf(ang);
}

__device__ __forceinline__ void mma_f16(float c[4], uint32_t a0, uint32_t a1,
        uint32_t a2, uint32_t a3, uint32_t b0, uint32_t b1) {
    asm volatile(
        "mma.sync.aligned.m16n8k16.row.col.f32.f16.f16.f32 "
        "{%0,%1,%2,%3}, {%4,%5,%6,%7}, {%8,%9}, {%0,%1,%2,%3};"
        : "+f"(c[0]), "+f"(c[1]), "+f"(c[2]), "+f"(c[3])
        : "r"(a0), "r"(a1), "r"(a2), "r"(a3), "r"(b0), "r"(b1));
}

__device__ __forceinline__ void ldsm4(uint32_t r[4], uint32_t addr) {
    asm volatile("ldmatrix.sync.aligned.m8n8.x4.shared.b16 {%0,%1,%2,%3}, [%4];"
        : "=r"(r[0]), "=r"(r[1]), "=r"(r[2]), "=r"(r[3]) : "r"(addr));
}
__device__ __forceinline__ void ldsm4t(uint32_t r[4], uint32_t addr) {
    asm volatile("ldmatrix.sync.aligned.m8n8.x4.trans.shared.b16 {%0,%1,%2,%3}, [%4];"
        : "=r"(r[0]), "=r"(r[1]), "=r"(r[2]), "=r"(r[3]) : "r"(addr));
}

__device__ __forceinline__ void cp16(void* dst, const void* src) {
    uint32_t d = (uint32_t)__cvta_generic_to_shared(dst);
    asm volatile("cp.async.cg.shared.global [%0], [%1], 16;" :: "r"(d), "l"(src));
}
__device__ __forceinline__ void cp16s(uint32_t dst_shared, const void* src) {
    asm volatile("cp.async.cg.shared.global [%0], [%1], 16;" :: "r"(dst_shared), "l"(src));
}
__device__ __forceinline__ void cp_commit() { asm volatile("cp.async.commit_group;"); }
__device__ __forceinline__ void cp_wait2()  { asm volatile("cp.async.wait_group 2;"); }
__device__ __forceinline__ void cp_wait0()  { asm volatile("cp.async.wait_group 0;"); }

// ---------------- FP16 tensor-core GEMM (128x128, 256 thr, 4-stage) ----------
#define ASTR 40
#define BSTR 264
#define A_STAGE_H (128*ASTR)
#define B_STAGE_H (32*BSTR)
#define A_STAGE_B (A_STAGE_H*2)
#define B_STAGE_B (B_STAGE_H*2)
#define NSTAGE 4
#define GEMM_SMEM_BYTES (NSTAGE*(A_STAGE_B + B_STAGE_B))   // 108544

template<int ACT, int RESID, int OUTH, int POS>
__global__ void __launch_bounds__(256) gemm_f16(
        const __half* __restrict__ A, const __half* __restrict__ B,
        const float* __restrict__ bias, void* __restrict__ Cv,
        int M, int N, int K)
{
    extern __shared__ uint32_t smem_dyn[];
    __half* Ash = (__half*)smem_dyn;
    __half* Bsh = (__half*)smem_dyn + NSTAGE*A_STAGE_H;
    uint32_t s_base = (uint32_t)__cvta_generic_to_shared(smem_dyn);
    uint32_t a_s32 = s_base;
    uint32_t b_s32 = s_base + NSTAGE*A_STAGE_B;

    int tid  = threadIdx.x;
    int lane = tid & 31;
    int warp = tid >> 5;
    int warp_m = (warp >> 2) * 64;
    int warp_n = (warp & 3) * 32;
    int gid = lane >> 2, tig = lane & 3;

    int row0 = blockIdx.y * 128, col0 = blockIdx.x * 128;

    int rowA = tid >> 1;
    int akh  = (tid & 1) * 16;
    int arow = row0 + rowA; if (arow >= M) arow = M - 1;
    const __half* Aptr = A + (size_t)arow * K + akh;
    int rowB = tid >> 3;
    int nch  = (tid & 7) * 16;
    const __half* Bptr = B + (size_t)rowB * N + col0 + nch;

    uint32_t aoff = (uint32_t)((lane & 15) * (ASTR*2) + (lane >> 4) * 16);
    uint32_t boff = (uint32_t)((lane & 15) * (BSTR*2) + (lane >> 4) * 16);

    float acc[4][4][4];
#pragma unroll
    for (int i = 0; i < 4; i++)
#pragma unroll
        for (int j = 0; j < 4; j++)
#pragma unroll
            for (int r = 0; r < 4; r++) acc[i][j][r] = 0.f;

    int nt = K >> 5;

#pragma unroll
    for (int s = 0; s < NSTAGE - 1; s++) {
        const __half* ap = Aptr + (size_t)s * 32;
        cp16(Ash + (size_t)s*A_STAGE_H + rowA*ASTR + akh,     ap);
        cp16(Ash + (size_t)s*A_STAGE_H + rowA*ASTR + akh + 8, ap + 8);
        const __half* bp = Bptr + (size_t)s * 32 * N;
        cp16(Bsh + (size_t)s*B_STAGE_H + rowB*BSTR + nch,     bp);
        cp16(Bsh + (size_t)s*B_STAGE_H + rowB*BSTR + nch + 8, bp + 8);
        cp_commit();
    }

    for (int t = 0; t < nt; t++) {
        cp_wait2();
        __syncthreads();
        int buf = t % NSTAGE;
        uint32_t abase = a_s32 + buf*A_STAGE_B + warp_m*(ASTR*2) + aoff;
        uint32_t bbase = b_s32 + buf*B_STAGE_B + warp_n*2 + boff;
#pragma unroll
        for (int k16 = 0; k16 < 2; k16++) {
            uint32_t ak = abase + k16*32;
            uint32_t bk = bbase + k16*16*(BSTR*2);
            uint32_t afr[4][4];
#pragma unroll
            for (int ma = 0; ma < 4; ma++)
                ldsm4(afr[ma], ak + ma*16*(ASTR*2));
            uint32_t bq[2][4];
#pragma unroll
            for (int nb = 0; nb < 2; nb++)
                ldsm4t(bq[nb], bk + nb*32);
#pragma unroll
            for (int ma = 0; ma < 4; ma++) {
#pragma unroll
                for (int nb = 0; nb < 2; nb++) {
                    mma_f16(acc[ma][nb*2],   afr[ma][0], afr[ma][1], afr[ma][2], afr[ma][3],
                            bq[nb][0], bq[nb][1]);
                    mma_f16(acc[ma][nb*2+1], afr[ma][0], afr[ma][1], afr[ma][2], afr[ma][3],
                            bq[nb][2], bq[nb][3]);
                }
            }
        }
        if (t + NSTAGE - 1 < nt) {
            int s = (t + NSTAGE - 1) % NSTAGE;
            const __half* ap = Aptr + (size_t)(t + NSTAGE - 1) * 32;
            cp16(Ash + (size_t)s*A_STAGE_H + rowA*ASTR + akh,     ap);
            cp16(Ash + (size_t)s*A_STAGE_H + rowA*ASTR + akh + 8, ap + 8);
            const __half* bp = Bptr + (size_t)(t + NSTAGE - 1) * 32 * N;
            cp16(Bsh + (size_t)s*B_STAGE_H + rowB*BSTR + nch,     bp);
            cp16(Bsh + (size_t)s*B_STAGE_H + rowB*BSTR + nch + 8, bp + 8);
        }
        cp_commit();
    }

#pragma unroll
    for (int ma = 0; ma < 4; ma++) {
        int r_lo = row0 + warp_m + ma * 16 + gid;
        int r_hi = r_lo + 8;
#pragma unroll
        for (int na = 0; na < 4; na++) {
            int c = col0 + warp_n + na * 8 + tig * 2;
            float bc0 = bias[c], bc1 = bias[c + 1];
            if (r_lo < M) {
                float v0 = acc[ma][na][0] + bc0;
                float v1 = acc[ma][na][1] + bc1;
                if (ACT == 1) { v0 = gelu_exact(v0); v1 = gelu_exact(v1); }
                if (POS) {
                    int bb = r_lo / NPATCH, s = r_lo % NPATCH + 1;
                    size_t off = (size_t)(bb*SEQ + s) * N + c;
                    ((float*)Cv)[off]     = v0 + pos_emb(s, c);
                    ((float*)Cv)[off + 1] = v1 + pos_emb(s, c + 1);
                } else {
                    size_t off = (size_t)r_lo * N + c;
                    if (OUTH) {
                        *(__half2*)((__half*)Cv + off) = __floats2half2_rn(v0, v1);
                    } else if (RESID) {
                        ((float*)Cv)[off] += v0; ((float*)Cv)[off + 1] += v1;
                    } else {
                        ((float*)Cv)[off]  = v0; ((float*)Cv)[off + 1]  = v1;
                    }
                }
            }
            if (r_hi < M) {
                float v2 = acc[ma][na][2] + bc0;
                float v3 = acc[ma][na][3] + bc1;
                if (ACT == 1) { v2 = gelu_exact(v2); v3 = gelu_exact(v3); }
                if (POS) {
                    int bb = r_hi / NPATCH, s = r_hi % NPATCH + 1;
                    size_t off = (size_t)(bb*SEQ + s) * N + c;
                    ((float*)Cv)[off]     = v2 + pos_emb(s, c);
                    ((float*)Cv)[off + 1] = v3 + pos_emb(s, c + 1);
                } else {
                    size_t off = (size_t)r_hi * N + c;
                    if (OUTH) {
                        *(__half2*)((__half*)Cv + off) = __floats2half2_rn(v2, v3);
                    } else if (RESID) {
                        ((float*)Cv)[off] += v2; ((float*)Cv)[off + 1] += v3;
                    } else {
                        ((float*)Cv)[off]  = v2; ((float*)Cv)[off + 1]  = v3;
                    }
                }
            }
        }
    }
}

// ---------------- QKV via tensor cores: per-head 128x64x64 mma ----------------
__global__ void __launch_bounds__(256) qkv_mma_kernel(const __half* __restrict__ x,
        const __half* __restrict__ Wq, const float* __restrict__ bq, __half* __restrict__ oq,
        const __half* __restrict__ Wk, const float* __restrict__ bk, __half* __restrict__ ok,
        const __half* __restrict__ Wv, const float* __restrict__ bv, __half* __restrict__ ov) {
    const __half* W; const float* bias; __half* outp;
    if (blockIdx.z == 0)      { W = Wq; bias = bq; outp = oq; }
    else if (blockIdx.z == 1) { W = Wk; bias = bk; outp = ok; }
    else                      { W = Wv; bias = bv; outp = ov; }

    __shared__ __align__(16) __half Xs[128][72];
    __shared__ __align__(16) __half Ws[64][72];
    uint32_t xs32 = (uint32_t)__cvta_generic_to_shared(Xs);
    uint32_t ws32 = (uint32_t)__cvta_generic_to_shared(Ws);

    int tid = threadIdx.x;
    int lane = tid & 31, warp = tid >> 5;
    int gid = lane >> 2, tig = lane & 3;
    int h = blockIdx.y;
    int row0 = blockIdx.x * 128;

#pragma unroll
    for (int i = 0; i < 4; i++) {
        int op = tid + i * 256;
        int row = op >> 3, c = op & 7;
        int grow = row0 + row; if (grow >= BS) grow = BS - 1;
        cp16s(xs32 + row*144 + c*16, x + (size_t)grow*HID + h*DH + c*8);
    }
#pragma unroll
    for (int i = 0; i < 2; i++) {
        int op = tid + i * 256;
        int row = op >> 3, c = op & 7;
        cp16s(ws32 + row*144 + c*16, W + (size_t)h*DH*DH + row*DH + c*8);
    }
    cp_commit();
    cp_wait0();
    __syncthreads();

    float acc[4][2][4];
#pragma unroll
    for (int g = 0; g < 4; g++)
#pragma unroll
        for (int hf = 0; hf < 2; hf++)
#pragma unroll
            for (int r = 0; r < 4; r++) acc[g][hf][r] = 0.f;

#pragma unroll
    for (int k16 = 0; k16 < 4; k16++) {
        uint32_t afr[4];
        ldsm4(afr, xs32 + (warp*16 + (lane & 15))*144 + (lane >> 4)*16 + k16*32);
#pragma unroll
        for (int g = 0; g < 4; g++) {
            uint32_t kr[4];
            ldsm4(kr, ws32 + (g*16 + (lane & 15))*144 + (lane >> 4)*16 + k16*32);
            mma_f16(acc[g][0], afr[0], afr[1], afr[2], afr[3], kr[0], kr[2]);
            mma_f16(acc[g][1], afr[0], afr[1], afr[2], afr[3], kr[1], kr[3]);
        }
    }

    int r_lo = row0 + warp*16 + gid;
    int r_hi = r_lo + 8;
#pragma unroll
    for (int g = 0; g < 4; g++)
#pragma unroll
        for (int hf = 0; hf < 2; hf++) {
            int e = g*16 + hf*8 + tig*2;
            float bc0 = bias[h*DH + e], bc1 = bias[h*DH + e + 1];
            if (r_lo < BS)
                *(__half2*)(outp + (size_t)r_lo*HID + h*DH + e) =
                    __floats2half2_rn(acc[g][hf][0] + bc0, acc[g][hf][1] + bc1);
            if (r_hi < BS)
                *(__half2*)(outp + (size_t)r_hi*HID + h*DH + e) =
                    __floats2half2_rn(acc[g][hf][2] + bc0, acc[g][hf][3] + bc1);
        }
}

// ---------------- fused attention: register softmax, 2 CTA/SM ----------------
#define AT_Q_OFF 0
#define AT_K_OFF 9216
#define AT_V_OFF 41472
#define AT_P_OFF 73728
#define AT_PSTR  232
#define AT_SMEM  (AT_P_OFF + 64*AT_PSTR*2)   // 103424

__global__ void __launch_bounds__(256) attn_fused_kernel(
        const __half* __restrict__ qh, const __half* __restrict__ kh,
        const __half* __restrict__ vh, float* __restrict__ outp)
{
    extern __shared__ char smem[];
    uint32_t sb = (uint32_t)__cvta_generic_to_shared(smem);
    __half* P  = (__half*)(smem + AT_P_OFF);
    __shared__ float redA[2][64];
    __shared__ float redB[2][64];

    int tid = threadIdx.x;
    int lane = tid & 31, warp = tid >> 5;
    int gid = lane >> 2, tig = lane & 3;
    int bh = blockIdx.y;
    int b = bh / NH, h = bh % NH;
    int q0 = blockIdx.x * 64;

#pragma unroll
    for (int i = 0; i < 2; i++) {
        int op = tid + i * 256;
        int row = op >> 3, c = op & 7;
        int grow = q0 + row; if (grow > SEQ - 1) grow = SEQ - 1;
        cp16s(sb + AT_Q_OFF + row*144 + c*16, qh + (size_t)(b*SEQ + grow)*HID + h*DH + c*8);
    }
#pragma unroll
    for (int i = 0; i < 7; i++) {
        int op = tid + i * 256;
        int row = op >> 3, c = op & 7;
        int grow = row > SEQ - 1 ? SEQ - 1 : row;
        const size_t goff = (size_t)(b*SEQ + grow)*HID + h*DH + c*8;
        cp16s(sb + AT_K_OFF + row*144 + c*16, kh + goff);
        cp16s(sb + AT_V_OFF + row*144 + c*16, vh + goff);
    }
    cp_commit();
    cp_wait0();
    __syncthreads();

    int mt = warp >> 1;
    int nh_ = warp & 1;

    float s_[7][2][4];
#pragma unroll
    for (int j = 0; j < 7; j++)
#pragma unroll
        for (int hf = 0; hf < 2; hf++)
#pragma unroll
            for (int r = 0; r < 4; r++) s_[j][hf][r] = 0.f;

#pragma unroll
    for (int k16 = 0; k16 < 4; k16++) {
        uint32_t afr[4];
        ldsm4(afr, sb + AT_Q_OFF + (mt*16 + (lane & 15))*144 + (lane >> 4)*16 + k16*32);
#pragma unroll
        for (int j = 0; j < 7; j++) {
            int g = nh_ * 7 + j;
            uint32_t kr[4];
            ldsm4(kr, sb + AT_K_OFF + (g*16 + (lane & 15))*144 + (lane >> 4)*16 + k16*32);
            mma_f16(s_[j][0], afr[0], afr[1], afr[2], afr[3], kr[0], kr[2]);
            mma_f16(s_[j][1], afr[0], afr[1], afr[2], afr[3], kr[1], kr[3]);
        }
    }

    // scale in-register
#pragma unroll
    for (int j = 0; j < 7; j++)
#pragma unroll
        for (int hf = 0; hf < 2; hf++)
#pragma unroll
            for (int r = 0; r < 4; r++) s_[j][hf][r] *= 0.125f;

    int row_lo = mt*16 + gid, row_hi = row_lo + 8;

    // ---- row max (register + quad shuffle + cross-warp smem) ----
    float mx_lo = -1e30f, mx_hi = -1e30f;
#pragma unroll
    for (int j = 0; j < 7; j++)
#pragma unroll
        for (int hf = 0; hf < 2; hf++) {
            int c0 = (nh_*7 + j)*16 + hf*8 + tig*2;
            if (c0 < SEQ)     { mx_lo = fmaxf(mx_lo, s_[j][hf][0]); mx_hi = fmaxf(mx_hi, s_[j][hf][2]); }
            if (c0 + 1 < SEQ) { mx_lo = fmaxf(mx_lo, s_[j][hf][1]); mx_hi = fmaxf(mx_hi, s_[j][hf][3]); }
        }
    mx_lo = fmaxf(mx_lo, __shfl_xor_sync(0xffffffffu, mx_lo, 1));
    mx_lo = fmaxf(mx_lo, __shfl_xor_sync(0xffffffffu, mx_lo, 2));
    mx_hi = fmaxf(mx_hi, __shfl_xor_sync(0xffffffffu, mx_hi, 1));
    mx_hi = fmaxf(mx_hi, __shfl_xor_sync(0xffffffffu, mx_hi, 2));
    if (tig == 0) { redA[nh_][row_lo] = mx_lo; redA[nh_][row_hi] = mx_hi; }
    __syncthreads();
    float m_lo = fmaxf(redA[0][row_lo], redA[1][row_lo]);
    float m_hi = fmaxf(redA[0][row_hi], redA[1][row_hi]);

    // ---- exp + row sum ----
    float sum_lo = 0.f, sum_hi = 0.f;
#pragma unroll
    for (int j = 0; j < 7; j++)
#pragma unroll
        for (int hf = 0; hf < 2; hf++) {
            int c0 = (nh_*7 + j)*16 + hf*8 + tig*2;
            float e0 = 0.f, e1 = 0.f, e2 = 0.f, e3 = 0.f;
            if (c0 < SEQ)     { e0 = expf(s_[j][hf][0] - m_lo); e2 = expf(s_[j][hf][2] - m_hi); }
            if (c0 + 1 < SEQ) { e1 = expf(s_[j][hf][1] - m_lo); e3 = expf(s_[j][hf][3] - m_hi); }
            s_[j][hf][0] = e0; s_[j][hf][1] = e1; s_[j][hf][2] = e2; s_[j][hf][3] = e3;
            sum_lo += e0 + e1; sum_hi += e2 + e3;
        }
    sum_lo += __shfl_xor_sync(0xffffffffu, sum_lo, 1);
    sum_lo += __shfl_xor_sync(0xffffffffu, sum_lo, 2);
    sum_hi += __shfl_xor_sync(0xffffffffu, sum_hi, 1);
    sum_hi += __shfl_xor_sync(0xffffffffu, sum_hi, 2);
    if (tig == 0) { redB[nh_][row_lo] = sum_lo; redB[nh_][row_hi] = sum_hi; }
    __syncthreads();
    float inv_lo = 1.0f / (redB[0][row_lo] + redB[1][row_lo]);
    float inv_hi = 1.0f / (redB[0][row_hi] + redB[1][row_hi]);

    // ---- write normalized P (half); masked cols are exactly 0 ----
#pragma unroll
    for (int j = 0; j < 7; j++)
#pragma unroll
        for (int hf = 0; hf < 2; hf++) {
            int c0 = (nh_*7 + j)*16 + hf*8 + tig*2;
            *(__half2*)(P + row_lo*AT_PSTR + c0) =
                __floats2half2_rn(s_[j][hf][0]*inv_lo, s_[j][hf][1]*inv_lo);
            *(__half2*)(P + row_hi*AT_PSTR + c0) =
                __floats2half2_rn(s_[j][hf][2]*inv_hi, s_[j][hf][3]*inv_hi);
        }
    __syncthreads();

    // ---- O = P V ----
    float o_[2][2][4];
#pragma unroll
    for (int g2 = 0; g2 < 2; g2++)
#pragma unroll
        for (int m2 = 0; m2 < 2; m2++)
#pragma unroll
            for (int r = 0; r < 4; r++) o_[g2][m2][r] = 0.f;

#pragma unroll
    for (int k16 = 0; k16 < 14; k16++) {
        uint32_t pfr[4];
        ldsm4(pfr, sb + AT_P_OFF + (mt*16 + (lane & 15))*(AT_PSTR*2) + (lane >> 4)*16 + k16*32);
#pragma unroll
        for (int g2 = 0; g2 < 2; g2++) {
            uint32_t vr[4];
            ldsm4t(vr, sb + AT_V_OFF + (k16*16 + (lane & 15))*144 + (lane >> 4)*16 + (nh_*32 + g2*16)*2);
            mma_f16(o_[g2][0], pfr[0], pfr[1], pfr[2], pfr[3], vr[0], vr[1]);
            mma_f16(o_[g2][1], pfr[0], pfr[1], pfr[2], pfr[3], vr[2], vr[3]);
        }
    }
#pragma unroll
    for (int g2 = 0; g2 < 2; g2++)
#pragma unroll
        for (int m2 = 0; m2 < 2; m2++) {
            int col = h*DH + nh_*32 + g2*16 + m2*8 + tig*2;
            int r_lo = q0 + mt*16 + gid;
            int r_hi = r_lo + 8;
            if (r_lo < SEQ) {
                size_t off = (size_t)(b*SEQ + r_lo)*HID + col;
                outp[off]     += o_[g2][m2][0];
                outp[off + 1] += o_[g2][m2][1];
            }
            if (r_hi < SEQ) {
                size_t off = (size_t)(b*SEQ + r_hi)*HID + col;
                outp[off]     += o_[g2][m2][2];
                outp[off + 1] += o_[g2][m2][3];
            }
        }
}

// ---------------- LayerNorm -> half output ----------------
__global__ void __launch_bounds__(256) ln_kernel(const float* __restrict__ in,
        const float* __restrict__ gam, const float* __restrict__ bet,
        __half* __restrict__ outp) {
    __shared__ float red[16];
    int row = blockIdx.x;
    int tid = threadIdx.x;
    const float* x = in + (size_t)row * HID;
    float v0 = x[tid], v1 = x[tid+256], v2 = x[tid+512];
    float s  = v0 + v1 + v2;
    float ss = v0*v0 + v1*v1 + v2*v2;
#pragma unroll
    for (int o = 16; o; o >>= 1) {
        s  += __shfl_xor_sync(0xffffffffu, s, o);
        ss += __shfl_xor_sync(0xffffffffu, ss, o);
    }
    if ((tid & 31) == 0) { red[tid>>5] = s; red[8 + (tid>>5)] = ss; }
    __syncthreads();
    if (tid < 32) {
        float a  = (tid < 8) ? red[tid]   : 0.f;
        float bb = (tid < 8) ? red[8+tid] : 0.f;
#pragma unroll
        for (int o = 4; o; o >>= 1) {
            a  += __shfl_xor_sync(0xffffffffu, a, o);
            bb += __shfl_xor_sync(0xffffffffu, bb, o);
        }
        if (tid == 0) { red[0] = a; red[1] = bb; }
    }
    __syncthreads();
    float mean = red[0] * (1.0f/768.0f);
    float var  = red[1] * (1.0f/768.0f) - mean*mean;
    float rstd = rsqrtf(var + 1e-5f);
    __half* o = outp + (size_t)row * HID;
    o[tid]     = __float2half((v0 - mean)*rstd*gam[tid]     + bet[tid]);
    o[tid+256] = __float2half((v1 - mean)*rstd*gam[tid+256] + bet[tid+256]);
    o[tid+512] = __float2half((v2 - mean)*rstd*gam[tid+512] + bet[tid+512]);
}

// ---------------- head ----------------
__global__ void __launch_bounds__(256) head_kernel(const float* __restrict__ xin,
        const float* __restrict__ Wo, const float* __restrict__ bo,
        float* __restrict__ res) {
    __shared__ float xs[HID];
    __shared__ float logits[OUTD];
    __shared__ float red[8];
    int b = blockIdx.x;
    int tid = threadIdx.x;
    const float* src = xin + (size_t)b*SEQ*HID;
    xs[tid] = src[tid]; xs[tid+256] = src[tid+256]; xs[tid+512] = src[tid+512];
    __syncthreads();
    for (int c = tid; c < OUTD; c += 256) {
        float acc = bo[c];
#pragma unroll 8
        for (int k2 = 0; k2 < HID; k2++) acc += xs[k2] * Wo[(size_t)k2*OUTD + c];
        logits[c] = acc;
    }
    __syncthreads();
    float m = -1e30f;
    for (int c = tid; c < OUTD; c += 256) m = fmaxf(m, logits[c]);
#pragma unroll
    for (int o = 16; o; o >>= 1) m = fmaxf(m, __shfl_xor_sync(0xffffffffu, m, o));
    if ((tid & 31) == 0) red[tid>>5] = m;
    __syncthreads();
    if (tid < 32) {
        float a = (tid < 8) ? red[tid] : -1e30f;
#pragma unroll
        for (int o = 4; o; o >>= 1) a = fmaxf(a, __shfl_xor_sync(0xffffffffu, a, o));
        if (tid == 0) red[0] = a;
    }
    __syncthreads();
    m = red[0];
    __syncthreads();
    float s = 0.f;
    for (int c = tid; c < OUTD; c += 256) { float e = expf(logits[c] - m); logits[c] = e; s += e; }
#pragma unroll
    for (int o = 16; o; o >>= 1) s += __shfl_xor_sync(0xffffffffu, s, o);
    if ((tid & 31) == 0) red[tid>>5] = s;
    __syncthreads();
    if (tid < 32) {
        float a = (tid < 8) ? red[tid] : 0.f;
#pragma unroll
        for (int o = 4; o; o >>= 1) a += __shfl_xor_sync(0xffffffffu, a, o);
        if (tid == 0) red[0] = a;
    }
    __syncthreads();
    float inv = 1.0f / red[0];
    for (int c = tid; c < OUTD; c += 256) res[(size_t)b*OUTD + c] = logits[c]*inv;
}

// ---------------- launch ----------------
extern "C" void kernel_launch(void* const* d_in, const int* in_sizes, int n_in,
                              void* d_out, int out_size) {
    const float* images = (const float*)d_in[0];
    const float* Wp     = (const float*)d_in[1];
    const float* bp     = (const float*)d_in[2];
    const float* cls    = (const float*)d_in[3];
    const float* ln1_g  = (const float*)d_in[4];
    const float* ln1_b  = (const float*)d_in[5];
    const float* Wq     = (const float*)d_in[6];
    const float* bq     = (const float*)d_in[7];
    const float* Wk     = (const float*)d_in[8];
    const float* bk     = (const float*)d_in[9];
    const float* Wv     = (const float*)d_in[10];
    const float* bv     = (const float*)d_in[11];
    const float* ln2_g  = (const float*)d_in[12];
    const float* ln2_b  = (const float*)d_in[13];
    const float* W1     = (const float*)d_in[14];
    const float* b1     = (const float*)d_in[15];
    const float* W2     = (const float*)d_in[16];
    const float* b2     = (const float*)d_in[17];
    const float* Wo     = (const float*)d_in[18];
    const float* bo     = (const float*)d_in[19];
    float* outp = (float*)d_out;

    float *p_out;
    __half *p_xh, *p_ffh, *p_wh, *p_qh, *p_kh, *p_vh;
    cudaGetSymbolAddress((void**)&p_out, g_out);
    cudaGetSymbolAddress((void**)&p_xh,  g_xh);
    cudaGetSymbolAddress((void**)&p_ffh, g_ffh);
    cudaGetSymbolAddress((void**)&p_qh,  g_qh);
    cudaGetSymbolAddress((void**)&p_kh,  g_kh);
    cudaGetSymbolAddress((void**)&p_vh,  g_vh);
    cudaGetSymbolAddress((void**)&p_wh,  g_wh);

    const __half* hWp = p_wh;
    const __half* hW1 = p_wh + WPN;
    const __half* hW2 = p_wh + WPN + W1N;
    const __half* hWq = p_wh + WPN + W1N + W2N;
    const __half* hWk = hWq + WQN;
    const __half* hWv = hWk + WQN;

    static bool attr_set = false;
    if (!attr_set) {
        cudaFuncSetAttribute(gemm_f16<0,0,0,1>, cudaFuncAttributeMaxDynamicSharedMemorySize, GEMM_SMEM_BYTES);
        cudaFuncSetAttribute(gemm_f16<1,0,1,0>, cudaFuncAttributeMaxDynamicSharedMemorySize, GEMM_SMEM_BYTES);
        cudaFuncSetAttribute(gemm_f16<0,1,0,0>, cudaFuncAttributeMaxDynamicSharedMemorySize, GEMM_SMEM_BYTES);
        cudaFuncSetAttribute(attn_fused_kernel, cudaFuncAttributeMaxDynamicSharedMemorySize, AT_SMEM);
        attr_set = true;
    }

    // 0) convert weights to half
    convert_weights_kernel<<<(WTOT + 255)/256, 256>>>(Wp, W1, W2, Wq, Wk, Wv, p_wh);

    // 1) patchify + patch embedding (pos-emb fused) + cls rows
    patchify_kernel<<<(BP*HID + 255)/256, 256>>>(images, p_xh);
    gemm_f16<0,0,0,1><<<dim3(HID/128, (BP+127)/128), 256, GEMM_SMEM_BYTES>>>(p_xh, hWp, bp, p_out, BP, HID, HID);
    cls_row_kernel<<<(BATCH*HID + 255)/256, 256>>>(cls, p_out);

    // 2) transformer layers
    for (int l = 0; l < NL; l++) {
        ln_kernel<<<BS, 256>>>(p_out, ln1_g + l*HID, ln1_b + l*HID, p_xh);
        qkv_mma_kernel<<<dim3((BS+127)/128, NH, 3), 256>>>(p_xh,
            hWq + (size_t)l*NH*DH*DH, bq + l*NH*DH, p_qh,
            hWk + (size_t)l*NH*DH*DH, bk + l*NH*DH, p_kh,
            hWv + (size_t)l*NH*DH*DH, bv + l*NH*DH, p_vh);
        attn_fused_kernel<<<dim3(4, BATCH*NH), 256, AT_SMEM>>>(p_qh, p_kh, p_vh, p_out);
        ln_kernel<<<BS, 256>>>(p_out, ln2_g + l*HID, ln2_b + l*HID, p_xh);
        gemm_f16<1,0,1,0><<<dim3(DFF/128, (BS+127)/128), 256, GEMM_SMEM_BYTES>>>(p_xh, hW1 + (size_t)l*HID*DFF, b1 + l*DFF, p_ffh, BS, DFF, HID);
        gemm_f16<0,1,0,0><<<dim3(HID/128, (BS+127)/128), 256, GEMM_SMEM_BYTES>>>(p_ffh, hW2 + (size_t)l*DFF*HID, b2 + l*HID, p_out, BS, HID, DFF);
    }

    // 3) classification head + softmax
    head_kernel<<<BATCH, 256>>>(p_out, Wo, bo, outp);
}